// round 12
// baseline (speedup 1.0000x reference)
#include <cuda_runtime.h>
#include <cuda_bf16.h>
#include <cstdint>

#define N_NODE 100000
#define N_EDGE 1600000
#define D      128
#define DE     16
#define FULLM  0xFFFFFFFFu
#define NBLK   98          // ceil(N_NODE / 1024)

// ---------------------------------------------------------------------------
// Scratch (static device arrays; allocation is forbidden)
// ---------------------------------------------------------------------------
__device__ int    g_cnt[N_NODE];
__device__ int    g_rank[N_EDGE];             // per-edge insertion rank
__device__ int    g_rowtmp[N_NODE + 1];       // block-local exclusive prefix
__device__ int    g_bsum[NBLK];
__device__ int    g_bpre[NBLK];
__device__ int4   g_slot[N_EDGE];             // (src_node, weight_bits, edge_idx, pad)
__device__ float4 g_h[(N_NODE + 64) * (D / 4)]; // fused pre-MLP activations

// ---------------------------------------------------------------------------
// f32x2 packed-FMA helpers (Blackwell FFMA2; bit-identical fp32 semantics)
// ---------------------------------------------------------------------------
__device__ __forceinline__ unsigned long long pack2(float a, float b)
{
    unsigned long long r;
    asm("mov.b64 %0, {%1, %2};" : "=l"(r) : "f"(a), "f"(b));
    return r;
}
__device__ __forceinline__ float2 unpack2(unsigned long long v)
{
    float2 r;
    asm("mov.b64 {%0, %1}, %2;" : "=f"(r.x), "=f"(r.y) : "l"(v));
    return r;
}
__device__ __forceinline__ void ffma2(unsigned long long& d,
                                      unsigned long long a,
                                      unsigned long long b)
{
    asm("fma.rn.f32x2 %0, %1, %2, %0;" : "+l"(d) : "l"(a), "l"(b));
}

// ---------------------------------------------------------------------------
// K1: histogram of destination nodes + per-edge rank
// ---------------------------------------------------------------------------
__global__ __launch_bounds__(256) void k_hist(const int2* __restrict__ edge_list)
{
    int e = blockIdx.x * blockDim.x + threadIdx.x;
    if (e < N_EDGE)
        g_rank[e] = atomicAdd(&g_cnt[edge_list[e].y], 1);
}

// ---------------------------------------------------------------------------
// K2a: per-1024-block exclusive scan
// ---------------------------------------------------------------------------
__global__ __launch_bounds__(1024) void k_scan1()
{
    __shared__ int sdata[1024];
    int t = threadIdx.x, b = blockIdx.x;
    int idx = b * 1024 + t;
    int v = (idx < N_NODE) ? g_cnt[idx] : 0;
    sdata[t] = v;
    __syncthreads();
    for (int off = 1; off < 1024; off <<= 1) {
        int u = (t >= off) ? sdata[t - off] : 0;
        __syncthreads();
        sdata[t] += u;
        __syncthreads();
    }
    if (idx < N_NODE) g_rowtmp[idx] = sdata[t] - v;   // exclusive within block
    if (t == 1023) g_bsum[b] = sdata[1023];
}

// ---------------------------------------------------------------------------
// K2b: scan of block sums + sentinel
// ---------------------------------------------------------------------------
__global__ __launch_bounds__(128) void k_scan2()
{
    __shared__ int sdata[128];
    int t = threadIdx.x;
    int v = (t < NBLK) ? g_bsum[t] : 0;
    sdata[t] = v;
    __syncthreads();
    for (int off = 1; off < 128; off <<= 1) {
        int u = (t >= off) ? sdata[t - off] : 0;
        __syncthreads();
        sdata[t] += u;
        __syncthreads();
    }
    if (t < NBLK) g_bpre[t] = sdata[t] - v;
    // sentinel: rowtmp[N_NODE] + bpre[N_NODE>>10] == N_EDGE
    if (t == (N_NODE >> 10)) {
        int bpre_here = sdata[t] - v;
        g_rowtmp[N_NODE] = sdata[127] - bpre_here;
    }
}

// ---------------------------------------------------------------------------
// K3: reorder edges into CSR slots (rank-based, no atomics, no feature work)
// ---------------------------------------------------------------------------
__global__ __launch_bounds__(256) void k_reorder(
    const int2*  __restrict__ edge_list,
    const float* __restrict__ edge_weight)
{
    int e = blockIdx.x * blockDim.x + threadIdx.x;
    if (e >= N_EDGE) return;
    int2  nn = edge_list[e];
    float w  = edge_weight[e];
    int slot = g_rowtmp[nn.y] + g_bpre[nn.y >> 10] + g_rank[e];
    g_slot[slot] = make_int4(nn.x, __float_as_int(w), e, 0);
}

// ---------------------------------------------------------------------------
// K4: gather-reduce.  One warp per node, edge loop unrolled x4.
//   h[node] = x[node] + sum_e w*x[src] + (sum_e w*ef[e]) @ W_edge + b_edge
// Edge-feature rows gathered inline (lanes 0..3, one 64B txn per edge).
// ---------------------------------------------------------------------------
__global__ __launch_bounds__(256) void k_gather(
    const float* __restrict__ x,
    const float* __restrict__ edge_feat,  // (N_EDGE, 16)
    const float* __restrict__ We,         // (16, 128)
    const float* __restrict__ be)         // (128,)
{
    const int node = blockIdx.x * 8 + (threadIdx.x >> 5);
    const int lane = threadIdx.x & 31;

    const float4* x4  = (const float4*)x;
    const float4* ef4 = (const float4*)edge_feat;
    const float4* We4 = (const float4*)We;
    const float4* be4 = (const float4*)be;

    const int s = g_rowtmp[node]     + g_bpre[node >> 10];
    const int e = g_rowtmp[node + 1] + g_bpre[(node + 1) >> 10];

    float4 acc = make_float4(0.f, 0.f, 0.f, 0.f);
    float4 ea  = make_float4(0.f, 0.f, 0.f, 0.f);
    const bool efl = (lane < (DE / 4));

    int j = s;
    for (; j + 4 <= e; j += 4) {
        int4 s0 = g_slot[j + 0];
        int4 s1 = g_slot[j + 1];
        int4 s2 = g_slot[j + 2];
        int4 s3 = g_slot[j + 3];
        float4 v0 = x4[(size_t)s0.x * (D / 4) + lane];
        float4 v1 = x4[(size_t)s1.x * (D / 4) + lane];
        float4 v2 = x4[(size_t)s2.x * (D / 4) + lane];
        float4 v3 = x4[(size_t)s3.x * (D / 4) + lane];
        float w0 = __int_as_float(s0.y);
        float w1 = __int_as_float(s1.y);
        float w2 = __int_as_float(s2.y);
        float w3 = __int_as_float(s3.y);
        acc.x += w0 * v0.x + w1 * v1.x + w2 * v2.x + w3 * v3.x;
        acc.y += w0 * v0.y + w1 * v1.y + w2 * v2.y + w3 * v3.y;
        acc.z += w0 * v0.z + w1 * v1.z + w2 * v2.z + w3 * v3.z;
        acc.w += w0 * v0.w + w1 * v1.w + w2 * v2.w + w3 * v3.w;
        if (efl) {
            float4 f0 = ef4[(size_t)s0.z * (DE / 4) + lane];
            float4 f1 = ef4[(size_t)s1.z * (DE / 4) + lane];
            float4 f2 = ef4[(size_t)s2.z * (DE / 4) + lane];
            float4 f3 = ef4[(size_t)s3.z * (DE / 4) + lane];
            ea.x += w0 * f0.x + w1 * f1.x + w2 * f2.x + w3 * f3.x;
            ea.y += w0 * f0.y + w1 * f1.y + w2 * f2.y + w3 * f3.y;
            ea.z += w0 * f0.z + w1 * f1.z + w2 * f2.z + w3 * f3.z;
            ea.w += w0 * f0.w + w1 * f1.w + w2 * f2.w + w3 * f3.w;
        }
    }
    for (; j < e; j++) {
        int4 sv = g_slot[j];
        float w = __int_as_float(sv.y);
        float4 v = x4[(size_t)sv.x * (D / 4) + lane];
        acc.x += w * v.x; acc.y += w * v.y;
        acc.z += w * v.z; acc.w += w * v.w;
        if (efl) {
            float4 f = ef4[(size_t)sv.z * (DE / 4) + lane];
            ea.x += w * f.x; ea.y += w * f.y;
            ea.z += w * f.z; ea.w += w * f.w;
        }
    }

    // eagg @ W_edge: ea lives in lanes 0..3 (lane sl holds k = 4*sl + c)
    #pragma unroll
    for (int sl = 0; sl < 4; sl++) {
        float e0 = __shfl_sync(FULLM, ea.x, sl);
        float e1 = __shfl_sync(FULLM, ea.y, sl);
        float e2 = __shfl_sync(FULLM, ea.z, sl);
        float e3 = __shfl_sync(FULLM, ea.w, sl);
        float4 w0 = We4[(4 * sl + 0) * (D / 4) + lane];
        float4 w1 = We4[(4 * sl + 1) * (D / 4) + lane];
        float4 w2 = We4[(4 * sl + 2) * (D / 4) + lane];
        float4 w3 = We4[(4 * sl + 3) * (D / 4) + lane];
        acc.x += e0 * w0.x + e1 * w1.x + e2 * w2.x + e3 * w3.x;
        acc.y += e0 * w0.y + e1 * w1.y + e2 * w2.y + e3 * w3.y;
        acc.z += e0 * w0.z + e1 * w1.z + e2 * w2.z + e3 * w3.z;
        acc.w += e0 * w0.w + e1 * w1.w + e2 * w2.w + e3 * w3.w;
    }

    float4 xs = x4[(size_t)node * (D / 4) + lane];
    float4 bb = be4[lane];
    acc.x += xs.x + bb.x; acc.y += xs.y + bb.y;
    acc.z += xs.z + bb.z; acc.w += xs.w + bb.w;
    g_h[(size_t)node * (D / 4) + lane] = acc;
}

// ---------------------------------------------------------------------------
// K5: node MLP with packed f32x2 FMAs (proven R4/R9 version).
// 64 nodes/block, 512 threads, 4 nodes x 4 cols per thread.
// ---------------------------------------------------------------------------
#define SH_STRIDE 132

__global__ __launch_bounds__(512, 1) void k_mlp(
    const float* __restrict__ W1,
    const float* __restrict__ b1,
    const float* __restrict__ W2,
    const float* __restrict__ b2,
    float* __restrict__ out)
{
    extern __shared__ float smem[];
    float* sW1 = smem;                 // 16384 floats
    float* sW2 = sW1 + 16384;          // 16384 floats
    float* sh  = sW2 + 16384;          // 64 * 132 floats

    const int tid  = threadIdx.x;
    const int base = blockIdx.x * 64;

    {
        const float4* W1v = (const float4*)W1;
        const float4* W2v = (const float4*)W2;
        float4* sW1v = (float4*)sW1;
        float4* sW2v = (float4*)sW2;
        #pragma unroll 4
        for (int i = tid; i < 4096; i += 512) { sW1v[i] = W1v[i]; sW2v[i] = W2v[i]; }
        // activation tile (g_h is padded past N_NODE, loads always in-bounds)
        for (int i = tid; i < 64 * 32; i += 512) {
            int n = i >> 5, c4 = i & 31;
            *(float4*)(sh + n * SH_STRIDE + c4 * 4) = g_h[(size_t)(base + n) * 32 + c4];
        }
    }
    __syncthreads();

    const int tx   = tid & 31;
    const int ty   = tid >> 5;       // 0..15
    const int col  = tx * 4;
    const int nrow = ty * 4;

    unsigned long long acc2[4][2];

    // ---- Layer 1 ----
    {
        const float4 bb = *(const float4*)(b1 + col);
        unsigned long long c01 = pack2(bb.x, bb.y);
        unsigned long long c23 = pack2(bb.z, bb.w);
        #pragma unroll
        for (int a = 0; a < 4; a++) { acc2[a][0] = c01; acc2[a][1] = c23; }
    }
    #pragma unroll 4
    for (int k = 0; k < 128; k++) {
        const ulonglong2 wv = *(const ulonglong2*)(sW1 + k * 128 + col);
        float h0 = sh[(nrow + 0) * SH_STRIDE + k];
        float h1 = sh[(nrow + 1) * SH_STRIDE + k];
        float h2 = sh[(nrow + 2) * SH_STRIDE + k];
        float h3 = sh[(nrow + 3) * SH_STRIDE + k];
        unsigned long long p0 = pack2(h0, h0);
        unsigned long long p1 = pack2(h1, h1);
        unsigned long long p2 = pack2(h2, h2);
        unsigned long long p3 = pack2(h3, h3);
        ffma2(acc2[0][0], p0, wv.x); ffma2(acc2[0][1], p0, wv.y);
        ffma2(acc2[1][0], p1, wv.x); ffma2(acc2[1][1], p1, wv.y);
        ffma2(acc2[2][0], p2, wv.x); ffma2(acc2[2][1], p2, wv.y);
        ffma2(acc2[3][0], p3, wv.x); ffma2(acc2[3][1], p3, wv.y);
    }
    __syncthreads();
    #pragma unroll
    for (int a = 0; a < 4; a++) {
        float2 q0 = unpack2(acc2[a][0]);
        float2 q1 = unpack2(acc2[a][1]);
        float4 r;
        r.x = fmaxf(q0.x, 0.f); r.y = fmaxf(q0.y, 0.f);
        r.z = fmaxf(q1.x, 0.f); r.w = fmaxf(q1.y, 0.f);
        *(float4*)(sh + (nrow + a) * SH_STRIDE + col) = r;
    }
    __syncthreads();

    // ---- Layer 2 ----
    {
        const float4 bb = *(const float4*)(b2 + col);
        unsigned long long c01 = pack2(bb.x, bb.y);
        unsigned long long c23 = pack2(bb.z, bb.w);
        #pragma unroll
        for (int a = 0; a < 4; a++) { acc2[a][0] = c01; acc2[a][1] = c23; }
    }
    #pragma unroll 4
    for (int k = 0; k < 128; k++) {
        const ulonglong2 wv = *(const ulonglong2*)(sW2 + k * 128 + col);
        float h0 = sh[(nrow + 0) * SH_STRIDE + k];
        float h1 = sh[(nrow + 1) * SH_STRIDE + k];
        float h2 = sh[(nrow + 2) * SH_STRIDE + k];
        float h3 = sh[(nrow + 3) * SH_STRIDE + k];
        unsigned long long p0 = pack2(h0, h0);
        unsigned long long p1 = pack2(h1, h1);
        unsigned long long p2 = pack2(h2, h2);
        unsigned long long p3 = pack2(h3, h3);
        ffma2(acc2[0][0], p0, wv.x); ffma2(acc2[0][1], p0, wv.y);
        ffma2(acc2[1][0], p1, wv.x); ffma2(acc2[1][1], p1, wv.y);
        ffma2(acc2[2][0], p2, wv.x); ffma2(acc2[2][1], p2, wv.y);
        ffma2(acc2[3][0], p3, wv.x); ffma2(acc2[3][1], p3, wv.y);
    }

    #pragma unroll
    for (int a = 0; a < 4; a++) {
        int node = base + nrow + a;
        if (node < N_NODE) {
            float2 q0 = unpack2(acc2[a][0]);
            float2 q1 = unpack2(acc2[a][1]);
            float4 r;
            r.x = fmaxf(q0.x, 0.f); r.y = fmaxf(q0.y, 0.f);
            r.z = fmaxf(q1.x, 0.f); r.w = fmaxf(q1.y, 0.f);
            *(float4*)(out + (size_t)node * D + col) = r;
        }
    }
}

// ---------------------------------------------------------------------------
// Launch
// ---------------------------------------------------------------------------
extern "C" void kernel_launch(void* const* d_in, const int* in_sizes, int n_in,
                              void* d_out, int out_size)
{
    const int2*  edge_list   = (const int2*)d_in[0];
    const float* edge_weight = (const float*)d_in[1];
    const float* edge_feat   = (const float*)d_in[2];
    // d_in[3] = num_node (constant)
    const float* x  = (const float*)d_in[4];
    const float* We = (const float*)d_in[5];
    const float* be = (const float*)d_in[6];
    const float* W1 = (const float*)d_in[7];
    const float* b1 = (const float*)d_in[8];
    const float* W2 = (const float*)d_in[9];
    const float* b2 = (const float*)d_in[10];
    float* out = (float*)d_out;

    const int smem_bytes = (16384 * 2 + 64 * SH_STRIDE) * 4;
    cudaFuncSetAttribute(k_mlp, cudaFuncAttributeMaxDynamicSharedMemorySize, smem_bytes);

    void* p_cnt = nullptr;
    cudaGetSymbolAddress(&p_cnt, g_cnt);
    cudaMemsetAsync(p_cnt, 0, sizeof(int) * N_NODE);

    k_hist<<<(N_EDGE + 255) / 256, 256>>>(edge_list);
    k_scan1<<<NBLK, 1024>>>();
    k_scan2<<<1, 128>>>();
    k_reorder<<<(N_EDGE + 255) / 256, 256>>>(edge_list, edge_weight);
    k_gather<<<N_NODE / 8, 256>>>(x, edge_feat, We, be);
    k_mlp<<<(N_NODE + 63) / 64, 512, smem_bytes>>>(W1, b1, W2, b2, out);
}

// round 13
// speedup vs baseline: 1.0394x; 1.0394x over previous
#include <cuda_runtime.h>
#include <cuda_bf16.h>
#include <cstdint>

#define N_NODE 100000
#define N_EDGE 1600000
#define D      128
#define DE     16
#define FULLM  0xFFFFFFFFu
#define NBLK   98          // ceil(N_NODE / 1024)

// ---------------------------------------------------------------------------
// Scratch (static device arrays; allocation is forbidden)
// ---------------------------------------------------------------------------
__device__ int    g_cnt[N_NODE];
__device__ int    g_rank[N_EDGE];             // per-edge insertion rank
__device__ int    g_rowtmp[N_NODE + 1];       // block-local exclusive prefix
__device__ int    g_bsum[NBLK];
__device__ int    g_bpre[NBLK];
__device__ int2   g_slot[N_EDGE];             // (src_node, weight_bits)
__device__ float4 g_eagg[N_NODE * (DE / 4)];  // 6.4 MB

// ---------------------------------------------------------------------------
// f32x2 packed-FMA helpers (Blackwell FFMA2; bit-identical fp32 semantics)
// ---------------------------------------------------------------------------
__device__ __forceinline__ unsigned long long pack2(float a, float b)
{
    unsigned long long r;
    asm("mov.b64 %0, {%1, %2};" : "=l"(r) : "f"(a), "f"(b));
    return r;
}
__device__ __forceinline__ float2 unpack2(unsigned long long v)
{
    float2 r;
    asm("mov.b64 {%0, %1}, %2;" : "=f"(r.x), "=f"(r.y) : "l"(v));
    return r;
}
__device__ __forceinline__ void ffma2(unsigned long long& d,
                                      unsigned long long a,
                                      unsigned long long b)
{
    asm("fma.rn.f32x2 %0, %1, %2, %0;" : "+l"(d) : "l"(a), "l"(b));
}
__device__ __forceinline__ void red_add_v4(float4* addr, float4 v)
{
    asm volatile("red.global.add.v4.f32 [%0], {%1, %2, %3, %4};"
                 :: "l"(addr), "f"(v.x), "f"(v.y), "f"(v.z), "f"(v.w)
                 : "memory");
}

// ---------------------------------------------------------------------------
// K1: histogram of destination nodes + per-edge rank
// ---------------------------------------------------------------------------
__global__ __launch_bounds__(256) void k_hist(const int2* __restrict__ edge_list)
{
    int e = blockIdx.x * blockDim.x + threadIdx.x;
    if (e < N_EDGE)
        g_rank[e] = atomicAdd(&g_cnt[edge_list[e].y], 1);
}

// ---------------------------------------------------------------------------
// K2a: per-1024-block exclusive scan (+ fold g_eagg zeroing in)
// ---------------------------------------------------------------------------
__global__ __launch_bounds__(1024) void k_scan1()
{
    __shared__ int sdata[1024];
    int t = threadIdx.x, b = blockIdx.x;
    int idx = b * 1024 + t;
    int v = (idx < N_NODE) ? g_cnt[idx] : 0;
    sdata[t] = v;

    // zero this node's eagg row (4 x float4, contiguous 64B per thread)
    if (idx < N_NODE) {
        const float4 z = make_float4(0.f, 0.f, 0.f, 0.f);
        float4* ez = &g_eagg[(size_t)idx * (DE / 4)];
        ez[0] = z; ez[1] = z; ez[2] = z; ez[3] = z;
    }
    __syncthreads();
    for (int off = 1; off < 1024; off <<= 1) {
        int u = (t >= off) ? sdata[t - off] : 0;
        __syncthreads();
        sdata[t] += u;
        __syncthreads();
    }
    if (idx < N_NODE) g_rowtmp[idx] = sdata[t] - v;   // exclusive within block
    if (t == 1023) g_bsum[b] = sdata[1023];
}

// ---------------------------------------------------------------------------
// K2b: scan of block sums + sentinel
// ---------------------------------------------------------------------------
__global__ __launch_bounds__(128) void k_scan2()
{
    __shared__ int sdata[128];
    int t = threadIdx.x;
    int v = (t < NBLK) ? g_bsum[t] : 0;
    sdata[t] = v;
    __syncthreads();
    for (int off = 1; off < 128; off <<= 1) {
        int u = (t >= off) ? sdata[t - off] : 0;
        __syncthreads();
        sdata[t] += u;
        __syncthreads();
    }
    if (t < NBLK) g_bpre[t] = sdata[t] - v;
    // sentinel: rowtmp[N_NODE] + bpre[N_NODE>>10] == N_EDGE
    if (t == (N_NODE >> 10)) {
        int bpre_here = sdata[t] - v;
        g_rowtmp[N_NODE] = sdata[127] - bpre_here;
    }
}

// ---------------------------------------------------------------------------
// K3: reorder edges into CSR slots + accumulate edge_agg (rank-based)
// edge_feat is streamed LINEARLY here (L2/DRAM friendly); eagg RMW hits a
// 6.4MB L2-resident array.
// ---------------------------------------------------------------------------
__global__ __launch_bounds__(256) void k_reorder(
    const int2*  __restrict__ edge_list,
    const float* __restrict__ edge_weight,
    const float* __restrict__ edge_feat)
{
    int e = blockIdx.x * blockDim.x + threadIdx.x;
    if (e >= N_EDGE) return;
    int2  nn = edge_list[e];
    float w  = edge_weight[e];
    int slot = g_rowtmp[nn.y] + g_bpre[nn.y >> 10] + g_rank[e];
    g_slot[slot] = make_int2(nn.x, __float_as_int(w));

    const float4* fr = (const float4*)(edge_feat + (size_t)e * DE);
    #pragma unroll
    for (int i = 0; i < DE / 4; i++) {
        float4 f = fr[i];
        f.x *= w; f.y *= w; f.z *= w; f.w *= w;
        red_add_v4(&g_eagg[(size_t)nn.y * (DE / 4) + i], f);
    }
}

// ---------------------------------------------------------------------------
// K4: FUSED gather + MLP.  512 threads, 64 nodes/block.
// Phase A: each warp gathers 4 nodes (R11 gather body), h written directly
//          to the MLP smem tile (no g_h global roundtrip).
// Phase B: proven R4/R9 MLP (4 nodes x 4 cols per thread, FFMA2).
// ---------------------------------------------------------------------------
#define SH_STRIDE 132

__global__ __launch_bounds__(512, 1) void k_fused(
    const float* __restrict__ x,
    const float* __restrict__ We,   // (16, 128)
    const float* __restrict__ be,   // (128,)
    const float* __restrict__ W1,
    const float* __restrict__ b1,
    const float* __restrict__ W2,
    const float* __restrict__ b2,
    float* __restrict__ out)
{
    extern __shared__ float smem[];
    float* sW1 = smem;                 // 16384 floats
    float* sW2 = sW1 + 16384;          // 16384 floats
    float* sh  = sW2 + 16384;          // 64 * 132 floats

    const int tid  = threadIdx.x;
    const int base = blockIdx.x * 64;
    const int lane = tid & 31;
    const int wid  = tid >> 5;       // 0..15

    // Stage weights (disjoint from sh; single sync after gather phase)
    {
        const float4* W1v = (const float4*)W1;
        const float4* W2v = (const float4*)W2;
        float4* sW1v = (float4*)sW1;
        float4* sW2v = (float4*)sW2;
        #pragma unroll 4
        for (int i = tid; i < 4096; i += 512) { sW1v[i] = W1v[i]; sW2v[i] = W2v[i]; }
    }

    const float4* x4  = (const float4*)x;
    const float4* We4 = (const float4*)We;
    const float4* be4 = (const float4*)be;

    // ---- Phase A: gather 4 nodes per warp, write h into sh ----
    #pragma unroll 1
    for (int a = 0; a < 4; a++) {
        const int n    = wid * 4 + a;          // 0..63 within tile
        const int node = base + n;
        if (node >= N_NODE) break;             // tail tile: warp-uniform

        const int s = g_rowtmp[node]     + g_bpre[node >> 10];
        const int e = g_rowtmp[node + 1] + g_bpre[(node + 1) >> 10];

        float4 acc = make_float4(0.f, 0.f, 0.f, 0.f);

        int j = s;
        for (; j + 4 <= e; j += 4) {
            int2 s0 = g_slot[j + 0];
            int2 s1 = g_slot[j + 1];
            int2 s2 = g_slot[j + 2];
            int2 s3 = g_slot[j + 3];
            float4 v0 = x4[(size_t)s0.x * (D / 4) + lane];
            float4 v1 = x4[(size_t)s1.x * (D / 4) + lane];
            float4 v2 = x4[(size_t)s2.x * (D / 4) + lane];
            float4 v3 = x4[(size_t)s3.x * (D / 4) + lane];
            float w0 = __int_as_float(s0.y);
            float w1 = __int_as_float(s1.y);
            float w2 = __int_as_float(s2.y);
            float w3 = __int_as_float(s3.y);
            acc.x += w0 * v0.x + w1 * v1.x + w2 * v2.x + w3 * v3.x;
            acc.y += w0 * v0.y + w1 * v1.y + w2 * v2.y + w3 * v3.y;
            acc.z += w0 * v0.z + w1 * v1.z + w2 * v2.z + w3 * v3.z;
            acc.w += w0 * v0.w + w1 * v1.w + w2 * v2.w + w3 * v3.w;
        }
        for (; j < e; j++) {
            int2 sv = g_slot[j];
            float w = __int_as_float(sv.y);
            float4 v = x4[(size_t)sv.x * (D / 4) + lane];
            acc.x += w * v.x; acc.y += w * v.y;
            acc.z += w * v.z; acc.w += w * v.w;
        }

        // eagg @ W_edge: eagg row in lanes 0..3 (lane sl holds k = 4*sl + c)
        float4 ea = make_float4(0.f, 0.f, 0.f, 0.f);
        if (lane < (DE / 4)) ea = g_eagg[(size_t)node * (DE / 4) + lane];
        #pragma unroll
        for (int sl = 0; sl < 4; sl++) {
            float e0 = __shfl_sync(FULLM, ea.x, sl);
            float e1 = __shfl_sync(FULLM, ea.y, sl);
            float e2 = __shfl_sync(FULLM, ea.z, sl);
            float e3 = __shfl_sync(FULLM, ea.w, sl);
            float4 w0 = We4[(4 * sl + 0) * (D / 4) + lane];
            float4 w1 = We4[(4 * sl + 1) * (D / 4) + lane];
            float4 w2 = We4[(4 * sl + 2) * (D / 4) + lane];
            float4 w3 = We4[(4 * sl + 3) * (D / 4) + lane];
            acc.x += e0 * w0.x + e1 * w1.x + e2 * w2.x + e3 * w3.x;
            acc.y += e0 * w0.y + e1 * w1.y + e2 * w2.y + e3 * w3.y;
            acc.z += e0 * w0.z + e1 * w1.z + e2 * w2.z + e3 * w3.z;
            acc.w += e0 * w0.w + e1 * w1.w + e2 * w2.w + e3 * w3.w;
        }

        float4 xs = x4[(size_t)node * (D / 4) + lane];
        float4 bb = be4[lane];
        acc.x += xs.x + bb.x; acc.y += xs.y + bb.y;
        acc.z += xs.z + bb.z; acc.w += xs.w + bb.w;
        *(float4*)(sh + n * SH_STRIDE + lane * 4) = acc;
    }
    // Missing tail nodes: zero their sh rows so MLP math stays finite
    {
        int rem = N_NODE - base;            // >= 1
        if (rem < 64) {
            for (int i = tid; i < (64 - rem) * 32; i += 512) {
                int n = rem + (i >> 5), c4 = i & 31;
                *(float4*)(sh + n * SH_STRIDE + c4 * 4) = make_float4(0.f, 0.f, 0.f, 0.f);
            }
        }
    }
    __syncthreads();

    // ---- Phase B: MLP ----
    const int tx   = tid & 31;
    const int ty   = tid >> 5;
    const int col  = tx * 4;
    const int nrow = ty * 4;

    unsigned long long acc2[4][2];

    // Layer 1
    {
        const float4 bb = *(const float4*)(b1 + col);
        unsigned long long c01 = pack2(bb.x, bb.y);
        unsigned long long c23 = pack2(bb.z, bb.w);
        #pragma unroll
        for (int a = 0; a < 4; a++) { acc2[a][0] = c01; acc2[a][1] = c23; }
    }
    #pragma unroll 4
    for (int k = 0; k < 128; k++) {
        const ulonglong2 wv = *(const ulonglong2*)(sW1 + k * 128 + col);
        float h0 = sh[(nrow + 0) * SH_STRIDE + k];
        float h1 = sh[(nrow + 1) * SH_STRIDE + k];
        float h2 = sh[(nrow + 2) * SH_STRIDE + k];
        float h3 = sh[(nrow + 3) * SH_STRIDE + k];
        unsigned long long p0 = pack2(h0, h0);
        unsigned long long p1 = pack2(h1, h1);
        unsigned long long p2 = pack2(h2, h2);
        unsigned long long p3 = pack2(h3, h3);
        ffma2(acc2[0][0], p0, wv.x); ffma2(acc2[0][1], p0, wv.y);
        ffma2(acc2[1][0], p1, wv.x); ffma2(acc2[1][1], p1, wv.y);
        ffma2(acc2[2][0], p2, wv.x); ffma2(acc2[2][1], p2, wv.y);
        ffma2(acc2[3][0], p3, wv.x); ffma2(acc2[3][1], p3, wv.y);
    }
    __syncthreads();
    #pragma unroll
    for (int a = 0; a < 4; a++) {
        float2 q0 = unpack2(acc2[a][0]);
        float2 q1 = unpack2(acc2[a][1]);
        float4 r;
        r.x = fmaxf(q0.x, 0.f); r.y = fmaxf(q0.y, 0.f);
        r.z = fmaxf(q1.x, 0.f); r.w = fmaxf(q1.y, 0.f);
        *(float4*)(sh + (nrow + a) * SH_STRIDE + col) = r;
    }
    __syncthreads();

    // Layer 2
    {
        const float4 bb = *(const float4*)(b2 + col);
        unsigned long long c01 = pack2(bb.x, bb.y);
        unsigned long long c23 = pack2(bb.z, bb.w);
        #pragma unroll
        for (int a = 0; a < 4; a++) { acc2[a][0] = c01; acc2[a][1] = c23; }
    }
    #pragma unroll 4
    for (int k = 0; k < 128; k++) {
        const ulonglong2 wv = *(const ulonglong2*)(sW2 + k * 128 + col);
        float h0 = sh[(nrow + 0) * SH_STRIDE + k];
        float h1 = sh[(nrow + 1) * SH_STRIDE + k];
        float h2 = sh[(nrow + 2) * SH_STRIDE + k];
        float h3 = sh[(nrow + 3) * SH_STRIDE + k];
        unsigned long long p0 = pack2(h0, h0);
        unsigned long long p1 = pack2(h1, h1);
        unsigned long long p2 = pack2(h2, h2);
        unsigned long long p3 = pack2(h3, h3);
        ffma2(acc2[0][0], p0, wv.x); ffma2(acc2[0][1], p0, wv.y);
        ffma2(acc2[1][0], p1, wv.x); ffma2(acc2[1][1], p1, wv.y);
        ffma2(acc2[2][0], p2, wv.x); ffma2(acc2[2][1], p2, wv.y);
        ffma2(acc2[3][0], p3, wv.x); ffma2(acc2[3][1], p3, wv.y);
    }

    #pragma unroll
    for (int a = 0; a < 4; a++) {
        int node = base + nrow + a;
        if (node < N_NODE) {
            float2 q0 = unpack2(acc2[a][0]);
            float2 q1 = unpack2(acc2[a][1]);
            float4 r;
            r.x = fmaxf(q0.x, 0.f); r.y = fmaxf(q0.y, 0.f);
            r.z = fmaxf(q1.x, 0.f); r.w = fmaxf(q1.y, 0.f);
            *(float4*)(out + (size_t)node * D + col) = r;
        }
    }
}

// ---------------------------------------------------------------------------
// Launch
// ---------------------------------------------------------------------------
extern "C" void kernel_launch(void* const* d_in, const int* in_sizes, int n_in,
                              void* d_out, int out_size)
{
    const int2*  edge_list   = (const int2*)d_in[0];
    const float* edge_weight = (const float*)d_in[1];
    const float* edge_feat   = (const float*)d_in[2];
    // d_in[3] = num_node (constant)
    const float* x  = (const float*)d_in[4];
    const float* We = (const float*)d_in[5];
    const float* be = (const float*)d_in[6];
    const float* W1 = (const float*)d_in[7];
    const float* b1 = (const float*)d_in[8];
    const float* W2 = (const float*)d_in[9];
    const float* b2 = (const float*)d_in[10];
    float* out = (float*)d_out;

    const int smem_bytes = (16384 * 2 + 64 * SH_STRIDE) * 4;
    cudaFuncSetAttribute(k_fused, cudaFuncAttributeMaxDynamicSharedMemorySize, smem_bytes);

    void* p_cnt = nullptr;
    cudaGetSymbolAddress(&p_cnt, g_cnt);
    cudaMemsetAsync(p_cnt, 0, sizeof(int) * N_NODE);

    k_hist<<<(N_EDGE + 255) / 256, 256>>>(edge_list);
    k_scan1<<<NBLK, 1024>>>();
    k_scan2<<<1, 128>>>();
    k_reorder<<<(N_EDGE + 255) / 256, 256>>>(edge_list, edge_weight, edge_feat);
    k_fused<<<(N_NODE + 63) / 64, 512, smem_bytes>>>(x, We, be, W1, b1, W2, b2, out);
}

// round 14
// speedup vs baseline: 1.1468x; 1.1034x over previous
#include <cuda_runtime.h>
#include <cuda_bf16.h>
#include <cuda_fp16.h>
#include <cstdint>

#define N_NODE 100000
#define N_EDGE 1600000
#define D      128
#define DE     16
#define FULLM  0xFFFFFFFFu
#define NBLK   98          // ceil(N_NODE / 1024)

// ---------------------------------------------------------------------------
// Scratch (static device arrays; allocation is forbidden)
// ---------------------------------------------------------------------------
__device__ int    g_cnt[N_NODE];
__device__ int    g_rank[N_EDGE];             // per-edge insertion rank
__device__ int    g_rowtmp[N_NODE + 1];       // block-local exclusive prefix
__device__ int    g_bsum[NBLK];
__device__ int    g_bpre[NBLK];
__device__ int    g_done;                     // scan completion counter
__device__ int2   g_slot[N_EDGE];             // (src_node, weight_bits)
__device__ float4 g_eagg[N_NODE * (DE / 4)];  // 6.4 MB
__device__ uint2  g_xh[N_NODE * 32];          // x in fp16: 256B/row, 25.6MB
__device__ float4 g_h[(N_NODE + 64) * (D / 4)]; // fused pre-MLP activations

// ---------------------------------------------------------------------------
// helpers
// ---------------------------------------------------------------------------
__device__ __forceinline__ unsigned long long pack2(float a, float b)
{
    unsigned long long r;
    asm("mov.b64 %0, {%1, %2};" : "=l"(r) : "f"(a), "f"(b));
    return r;
}
__device__ __forceinline__ float2 unpack2(unsigned long long v)
{
    float2 r;
    asm("mov.b64 {%0, %1}, %2;" : "=f"(r.x), "=f"(r.y) : "l"(v));
    return r;
}
__device__ __forceinline__ void ffma2(unsigned long long& d,
                                      unsigned long long a,
                                      unsigned long long b)
{
    asm("fma.rn.f32x2 %0, %1, %2, %0;" : "+l"(d) : "l"(a), "l"(b));
}
__device__ __forceinline__ void red_add_v4(float4* addr, float4 v)
{
    asm volatile("red.global.add.v4.f32 [%0], {%1, %2, %3, %4};"
                 :: "l"(addr), "f"(v.x), "f"(v.y), "f"(v.z), "f"(v.w)
                 : "memory");
}
__device__ __forceinline__ float4 h4_to_f4(uint2 r)
{
    __half2 h0 = *reinterpret_cast<__half2*>(&r.x);
    __half2 h1 = *reinterpret_cast<__half2*>(&r.y);
    float2 a = __half22float2(h0);
    float2 b = __half22float2(h1);
    return make_float4(a.x, a.y, b.x, b.y);
}

// ---------------------------------------------------------------------------
// K1: histogram of destination nodes + per-edge rank
// ---------------------------------------------------------------------------
__global__ __launch_bounds__(256) void k_hist(const int2* __restrict__ edge_list)
{
    int e = blockIdx.x * blockDim.x + threadIdx.x;
    if (e < N_EDGE)
        g_rank[e] = atomicAdd(&g_cnt[edge_list[e].y], 1);
}

// ---------------------------------------------------------------------------
// K2: merged scan: fp16 conversion of x + block scan + (last block) scan of
// block sums.  98 blocks <= 148 SMs, last-block-done pattern.
// Also zeroes g_eagg.
// ---------------------------------------------------------------------------
__global__ __launch_bounds__(1024) void k_scan(const float4* __restrict__ x4)
{
    __shared__ int sdata[1024];
    __shared__ int sflag;
    const int t = threadIdx.x, b = blockIdx.x;
    const int idx = b * 1024 + t;

    // phase 0: convert x -> fp16 (coalesced grid-stride), zero eagg
    {
        const int gsz = NBLK * 1024;
        for (int i = b * 1024 + t; i < N_NODE * 32; i += gsz) {
            float4 v = x4[i];
            __half2 h0 = __floats2half2_rn(v.x, v.y);
            __half2 h1 = __floats2half2_rn(v.z, v.w);
            uint2 r;
            r.x = *reinterpret_cast<uint32_t*>(&h0);
            r.y = *reinterpret_cast<uint32_t*>(&h1);
            g_xh[i] = r;
        }
        if (idx < N_NODE) {
            const float4 z = make_float4(0.f, 0.f, 0.f, 0.f);
            float4* ez = &g_eagg[(size_t)idx * (DE / 4)];
            ez[0] = z; ez[1] = z; ez[2] = z; ez[3] = z;
        }
    }

    // phase 1: block-local exclusive scan of g_cnt
    int v = (idx < N_NODE) ? g_cnt[idx] : 0;
    sdata[t] = v;
    __syncthreads();
    for (int off = 1; off < 1024; off <<= 1) {
        int u = (t >= off) ? sdata[t - off] : 0;
        __syncthreads();
        sdata[t] += u;
        __syncthreads();
    }
    if (idx < N_NODE) g_rowtmp[idx] = sdata[t] - v;

    if (t == 1023) {
        g_bsum[b] = sdata[1023];
        __threadfence();
        int old = atomicAdd(&g_done, 1);
        sflag = (old == NBLK - 1) ? 1 : 0;
    }
    __syncthreads();

    // phase 2: last block scans the 98 block sums
    if (sflag) {
        __threadfence();   // acquire all g_bsum writes
        int v2 = 0;
        if (t < 128) {
            v2 = (t < NBLK) ? g_bsum[t] : 0;
            sdata[t] = v2;
        }
        __syncthreads();
        for (int off = 1; off < 128; off <<= 1) {
            int u = (t >= off && t < 128) ? sdata[t - off] : 0;
            __syncthreads();
            if (t < 128) sdata[t] += u;
            __syncthreads();
        }
        if (t < NBLK) g_bpre[t] = sdata[t] - v2;
        if (t == (N_NODE >> 10)) {
            int bpre_here = sdata[t] - v2;
            g_rowtmp[N_NODE] = sdata[127] - bpre_here;
        }
    }
}

// ---------------------------------------------------------------------------
// K3: reorder edges into CSR slots + accumulate edge_agg (rank-based).
// edge_feat streamed LINEARLY; eagg RMW hits 6.4MB L2-resident array.
// ---------------------------------------------------------------------------
__global__ __launch_bounds__(256) void k_reorder(
    const int2*  __restrict__ edge_list,
    const float* __restrict__ edge_weight,
    const float* __restrict__ edge_feat)
{
    int e = blockIdx.x * blockDim.x + threadIdx.x;
    if (e >= N_EDGE) return;
    int2  nn = edge_list[e];
    float w  = edge_weight[e];
    int slot = g_rowtmp[nn.y] + g_bpre[nn.y >> 10] + g_rank[e];
    g_slot[slot] = make_int2(nn.x, __float_as_int(w));

    const float4* fr = (const float4*)(edge_feat + (size_t)e * DE);
    #pragma unroll
    for (int i = 0; i < DE / 4; i++) {
        float4 f = fr[i];
        f.x *= w; f.y *= w; f.z *= w; f.w *= w;
        red_add_v4(&g_eagg[(size_t)nn.y * (DE / 4) + i], f);
    }
}

// ---------------------------------------------------------------------------
// K4: gather-reduce.  One warp per node, edge loop unrolled x4.
// Neighbor rows read from the fp16 cache (256B/row); fp32 accumulation.
// Self term + all weights stay fp32.
// ---------------------------------------------------------------------------
__global__ __launch_bounds__(256) void k_gather(
    const float* __restrict__ x,
    const float* __restrict__ We,   // (16, 128)
    const float* __restrict__ be)   // (128,)
{
    const int node = blockIdx.x * 8 + (threadIdx.x >> 5);
    const int lane = threadIdx.x & 31;

    const float4* x4  = (const float4*)x;
    const float4* We4 = (const float4*)We;
    const float4* be4 = (const float4*)be;

    const int s = g_rowtmp[node]     + g_bpre[node >> 10];
    const int e = g_rowtmp[node + 1] + g_bpre[(node + 1) >> 10];

    float4 acc = make_float4(0.f, 0.f, 0.f, 0.f);

    int j = s;
    for (; j + 4 <= e; j += 4) {
        int2 s0 = g_slot[j + 0];
        int2 s1 = g_slot[j + 1];
        int2 s2 = g_slot[j + 2];
        int2 s3 = g_slot[j + 3];
        uint2 r0 = g_xh[(size_t)s0.x * 32 + lane];
        uint2 r1 = g_xh[(size_t)s1.x * 32 + lane];
        uint2 r2 = g_xh[(size_t)s2.x * 32 + lane];
        uint2 r3 = g_xh[(size_t)s3.x * 32 + lane];
        float4 v0 = h4_to_f4(r0);
        float4 v1 = h4_to_f4(r1);
        float4 v2 = h4_to_f4(r2);
        float4 v3 = h4_to_f4(r3);
        float w0 = __int_as_float(s0.y);
        float w1 = __int_as_float(s1.y);
        float w2 = __int_as_float(s2.y);
        float w3 = __int_as_float(s3.y);
        acc.x += w0 * v0.x + w1 * v1.x + w2 * v2.x + w3 * v3.x;
        acc.y += w0 * v0.y + w1 * v1.y + w2 * v2.y + w3 * v3.y;
        acc.z += w0 * v0.z + w1 * v1.z + w2 * v2.z + w3 * v3.z;
        acc.w += w0 * v0.w + w1 * v1.w + w2 * v2.w + w3 * v3.w;
    }
    for (; j < e; j++) {
        int2 sv = g_slot[j];
        float w = __int_as_float(sv.y);
        float4 v = h4_to_f4(g_xh[(size_t)sv.x * 32 + lane]);
        acc.x += w * v.x; acc.y += w * v.y;
        acc.z += w * v.z; acc.w += w * v.w;
    }

    // eagg @ W_edge: eagg row in lanes 0..3 (lane sl holds k = 4*sl + c)
    float4 ea = make_float4(0.f, 0.f, 0.f, 0.f);
    if (lane < (DE / 4)) ea = g_eagg[(size_t)node * (DE / 4) + lane];
    #pragma unroll
    for (int sl = 0; sl < 4; sl++) {
        float e0 = __shfl_sync(FULLM, ea.x, sl);
        float e1 = __shfl_sync(FULLM, ea.y, sl);
        float e2 = __shfl_sync(FULLM, ea.z, sl);
        float e3 = __shfl_sync(FULLM, ea.w, sl);
        float4 w0 = We4[(4 * sl + 0) * (D / 4) + lane];
        float4 w1 = We4[(4 * sl + 1) * (D / 4) + lane];
        float4 w2 = We4[(4 * sl + 2) * (D / 4) + lane];
        float4 w3 = We4[(4 * sl + 3) * (D / 4) + lane];
        acc.x += e0 * w0.x + e1 * w1.x + e2 * w2.x + e3 * w3.x;
        acc.y += e0 * w0.y + e1 * w1.y + e2 * w2.y + e3 * w3.y;
        acc.z += e0 * w0.z + e1 * w1.z + e2 * w2.z + e3 * w3.z;
        acc.w += e0 * w0.w + e1 * w1.w + e2 * w2.w + e3 * w3.w;
    }

    // self term (fp32) + b_edge
    float4 xs = x4[(size_t)node * (D / 4) + lane];
    float4 bb = be4[lane];
    acc.x += xs.x + bb.x; acc.y += xs.y + bb.y;
    acc.z += xs.z + bb.z; acc.w += xs.w + bb.w;
    g_h[(size_t)node * (D / 4) + lane] = acc;
}

// ---------------------------------------------------------------------------
// K5: node MLP with packed f32x2 FMAs (proven R4/R9 version).
// 64 nodes/block, 512 threads, 4 nodes x 4 cols per thread.
// ---------------------------------------------------------------------------
#define SH_STRIDE 132

__global__ __launch_bounds__(512, 1) void k_mlp(
    const float* __restrict__ W1,
    const float* __restrict__ b1,
    const float* __restrict__ W2,
    const float* __restrict__ b2,
    float* __restrict__ out)
{
    extern __shared__ float smem[];
    float* sW1 = smem;                 // 16384 floats
    float* sW2 = sW1 + 16384;          // 16384 floats
    float* sh  = sW2 + 16384;          // 64 * 132 floats

    const int tid  = threadIdx.x;
    const int base = blockIdx.x * 64;

    {
        const float4* W1v = (const float4*)W1;
        const float4* W2v = (const float4*)W2;
        float4* sW1v = (float4*)sW1;
        float4* sW2v = (float4*)sW2;
        #pragma unroll 4
        for (int i = tid; i < 4096; i += 512) { sW1v[i] = W1v[i]; sW2v[i] = W2v[i]; }
        for (int i = tid; i < 64 * 32; i += 512) {
            int n = i >> 5, c4 = i & 31;
            *(float4*)(sh + n * SH_STRIDE + c4 * 4) = g_h[(size_t)(base + n) * 32 + c4];
        }
    }
    __syncthreads();

    const int tx   = tid & 31;
    const int ty   = tid >> 5;       // 0..15
    const int col  = tx * 4;
    const int nrow = ty * 4;

    unsigned long long acc2[4][2];

    // ---- Layer 1 ----
    {
        const float4 bb = *(const float4*)(b1 + col);
        unsigned long long c01 = pack2(bb.x, bb.y);
        unsigned long long c23 = pack2(bb.z, bb.w);
        #pragma unroll
        for (int a = 0; a < 4; a++) { acc2[a][0] = c01; acc2[a][1] = c23; }
    }
    #pragma unroll 4
    for (int k = 0; k < 128; k++) {
        const ulonglong2 wv = *(const ulonglong2*)(sW1 + k * 128 + col);
        float h0 = sh[(nrow + 0) * SH_STRIDE + k];
        float h1 = sh[(nrow + 1) * SH_STRIDE + k];
        float h2 = sh[(nrow + 2) * SH_STRIDE + k];
        float h3 = sh[(nrow + 3) * SH_STRIDE + k];
        unsigned long long p0 = pack2(h0, h0);
        unsigned long long p1 = pack2(h1, h1);
        unsigned long long p2 = pack2(h2, h2);
        unsigned long long p3 = pack2(h3, h3);
        ffma2(acc2[0][0], p0, wv.x); ffma2(acc2[0][1], p0, wv.y);
        ffma2(acc2[1][0], p1, wv.x); ffma2(acc2[1][1], p1, wv.y);
        ffma2(acc2[2][0], p2, wv.x); ffma2(acc2[2][1], p2, wv.y);
        ffma2(acc2[3][0], p3, wv.x); ffma2(acc2[3][1], p3, wv.y);
    }
    __syncthreads();
    #pragma unroll
    for (int a = 0; a < 4; a++) {
        float2 q0 = unpack2(acc2[a][0]);
        float2 q1 = unpack2(acc2[a][1]);
        float4 r;
        r.x = fmaxf(q0.x, 0.f); r.y = fmaxf(q0.y, 0.f);
        r.z = fmaxf(q1.x, 0.f); r.w = fmaxf(q1.y, 0.f);
        *(float4*)(sh + (nrow + a) * SH_STRIDE + col) = r;
    }
    __syncthreads();

    // ---- Layer 2 ----
    {
        const float4 bb = *(const float4*)(b2 + col);
        unsigned long long c01 = pack2(bb.x, bb.y);
        unsigned long long c23 = pack2(bb.z, bb.w);
        #pragma unroll
        for (int a = 0; a < 4; a++) { acc2[a][0] = c01; acc2[a][1] = c23; }
    }
    #pragma unroll 4
    for (int k = 0; k < 128; k++) {
        const ulonglong2 wv = *(const ulonglong2*)(sW2 + k * 128 + col);
        float h0 = sh[(nrow + 0) * SH_STRIDE + k];
        float h1 = sh[(nrow + 1) * SH_STRIDE + k];
        float h2 = sh[(nrow + 2) * SH_STRIDE + k];
        float h3 = sh[(nrow + 3) * SH_STRIDE + k];
        unsigned long long p0 = pack2(h0, h0);
        unsigned long long p1 = pack2(h1, h1);
        unsigned long long p2 = pack2(h2, h2);
        unsigned long long p3 = pack2(h3, h3);
        ffma2(acc2[0][0], p0, wv.x); ffma2(acc2[0][1], p0, wv.y);
        ffma2(acc2[1][0], p1, wv.x); ffma2(acc2[1][1], p1, wv.y);
        ffma2(acc2[2][0], p2, wv.x); ffma2(acc2[2][1], p2, wv.y);
        ffma2(acc2[3][0], p3, wv.x); ffma2(acc2[3][1], p3, wv.y);
    }

    #pragma unroll
    for (int a = 0; a < 4; a++) {
        int node = base + nrow + a;
        if (node < N_NODE) {
            float2 q0 = unpack2(acc2[a][0]);
            float2 q1 = unpack2(acc2[a][1]);
            float4 r;
            r.x = fmaxf(q0.x, 0.f); r.y = fmaxf(q0.y, 0.f);
            r.z = fmaxf(q1.x, 0.f); r.w = fmaxf(q1.y, 0.f);
            *(float4*)(out + (size_t)node * D + col) = r;
        }
    }
}

// ---------------------------------------------------------------------------
// Launch
// ---------------------------------------------------------------------------
extern "C" void kernel_launch(void* const* d_in, const int* in_sizes, int n_in,
                              void* d_out, int out_size)
{
    const int2*  edge_list   = (const int2*)d_in[0];
    const float* edge_weight = (const float*)d_in[1];
    const float* edge_feat   = (const float*)d_in[2];
    // d_in[3] = num_node (constant)
    const float* x  = (const float*)d_in[4];
    const float* We = (const float*)d_in[5];
    const float* be = (const float*)d_in[6];
    const float* W1 = (const float*)d_in[7];
    const float* b1 = (const float*)d_in[8];
    const float* W2 = (const float*)d_in[9];
    const float* b2 = (const float*)d_in[10];
    float* out = (float*)d_out;

    const int smem_bytes = (16384 * 2 + 64 * SH_STRIDE) * 4;
    cudaFuncSetAttribute(k_mlp, cudaFuncAttributeMaxDynamicSharedMemorySize, smem_bytes);

    void* p_cnt  = nullptr;
    void* p_done = nullptr;
    cudaGetSymbolAddress(&p_cnt,  g_cnt);
    cudaGetSymbolAddress(&p_done, g_done);
    cudaMemsetAsync(p_cnt,  0, sizeof(int) * N_NODE);
    cudaMemsetAsync(p_done, 0, sizeof(int));

    k_hist<<<(N_EDGE + 255) / 256, 256>>>(edge_list);                            // k1
    k_scan<<<NBLK, 1024>>>((const float4*)x);                                    // k2
    k_reorder<<<(N_EDGE + 255) / 256, 256>>>(edge_list, edge_weight, edge_feat); // k3
    k_gather<<<N_NODE / 8, 256>>>(x, We, be);                                    // k4 <- profiled
    k_mlp<<<(N_NODE + 63) / 64, 512, smem_bytes>>>(W1, b1, W2, b2, out);         // k5
}

// round 15
// speedup vs baseline: 1.3867x; 1.2092x over previous
#include <cuda_runtime.h>
#include <cuda_bf16.h>
#include <cuda_fp16.h>
#include <cstdint>

#define N_NODE 100000
#define N_EDGE 1600000
#define D      128
#define DE     16
#define FULLM  0xFFFFFFFFu
#define NBLK   98          // ceil(N_NODE / 1024)

// ---------------------------------------------------------------------------
// Scratch (static device arrays; allocation is forbidden)
// ---------------------------------------------------------------------------
__device__ int    g_cnt[N_NODE];
__device__ int    g_rank[N_EDGE];             // per-edge insertion rank
__device__ int    g_rowtmp[N_NODE + 1];       // block-local exclusive prefix
__device__ int    g_bsum[NBLK];
__device__ int    g_bpre[NBLK];
__device__ int    g_done;                     // scan completion counter
__device__ int2   g_slot[N_EDGE];             // (src_node, weight_bits)
__device__ float4 g_eagg[N_NODE * (DE / 4)];  // 6.4 MB
__device__ uint2  g_xh[N_NODE * 32];          // x in fp16: 256B/row, 25.6MB
__device__ float4 g_h[(N_NODE + 64) * (D / 4)]; // fused pre-MLP activations

// ---------------------------------------------------------------------------
// helpers
// ---------------------------------------------------------------------------
__device__ __forceinline__ void red_add_v4(float4* addr, float4 v)
{
    asm volatile("red.global.add.v4.f32 [%0], {%1, %2, %3, %4};"
                 :: "l"(addr), "f"(v.x), "f"(v.y), "f"(v.z), "f"(v.w)
                 : "memory");
}
__device__ __forceinline__ float4 h4_to_f4(uint2 r)
{
    __half2 h0 = *reinterpret_cast<__half2*>(&r.x);
    __half2 h1 = *reinterpret_cast<__half2*>(&r.y);
    float2 a = __half22float2(h0);
    float2 b = __half22float2(h1);
    return make_float4(a.x, a.y, b.x, b.y);
}
__device__ __forceinline__ unsigned f2tf(float f)
{
    unsigned r;
    asm("cvt.rna.tf32.f32 %0, %1;" : "=r"(r) : "f"(f));
    return r;
}
__device__ __forceinline__ void mma_tf32(
    float& d0, float& d1, float& d2, float& d3,
    unsigned a0, unsigned a1, unsigned a2, unsigned a3,
    unsigned b0, unsigned b1)
{
    asm("mma.sync.aligned.m16n8k8.row.col.f32.tf32.tf32.f32 "
        "{%0,%1,%2,%3},{%4,%5,%6,%7},{%8,%9},{%0,%1,%2,%3};"
        : "+f"(d0), "+f"(d1), "+f"(d2), "+f"(d3)
        : "r"(a0), "r"(a1), "r"(a2), "r"(a3), "r"(b0), "r"(b1));
}

// ---------------------------------------------------------------------------
// K1: histogram of destination nodes + per-edge rank
// ---------------------------------------------------------------------------
__global__ __launch_bounds__(256) void k_hist(const int2* __restrict__ edge_list)
{
    int e = blockIdx.x * blockDim.x + threadIdx.x;
    if (e < N_EDGE)
        g_rank[e] = atomicAdd(&g_cnt[edge_list[e].y], 1);
}

// ---------------------------------------------------------------------------
// K2: merged scan: fp16 conversion of x + block scan + (last block) scan of
// block sums.  98 blocks <= 148 SMs, last-block-done pattern.  Zeroes g_eagg.
// ---------------------------------------------------------------------------
__global__ __launch_bounds__(1024) void k_scan(const float4* __restrict__ x4)
{
    __shared__ int sdata[1024];
    __shared__ int sflag;
    const int t = threadIdx.x, b = blockIdx.x;
    const int idx = b * 1024 + t;

    // phase 0: convert x -> fp16 (coalesced grid-stride), zero eagg
    {
        const int gsz = NBLK * 1024;
        for (int i = b * 1024 + t; i < N_NODE * 32; i += gsz) {
            float4 v = x4[i];
            __half2 h0 = __floats2half2_rn(v.x, v.y);
            __half2 h1 = __floats2half2_rn(v.z, v.w);
            uint2 r;
            r.x = *reinterpret_cast<uint32_t*>(&h0);
            r.y = *reinterpret_cast<uint32_t*>(&h1);
            g_xh[i] = r;
        }
        if (idx < N_NODE) {
            const float4 z = make_float4(0.f, 0.f, 0.f, 0.f);
            float4* ez = &g_eagg[(size_t)idx * (DE / 4)];
            ez[0] = z; ez[1] = z; ez[2] = z; ez[3] = z;
        }
    }

    // phase 1: block-local exclusive scan of g_cnt
    int v = (idx < N_NODE) ? g_cnt[idx] : 0;
    sdata[t] = v;
    __syncthreads();
    for (int off = 1; off < 1024; off <<= 1) {
        int u = (t >= off) ? sdata[t - off] : 0;
        __syncthreads();
        sdata[t] += u;
        __syncthreads();
    }
    if (idx < N_NODE) g_rowtmp[idx] = sdata[t] - v;

    if (t == 1023) {
        g_bsum[b] = sdata[1023];
        __threadfence();
        int old = atomicAdd(&g_done, 1);
        sflag = (old == NBLK - 1) ? 1 : 0;
    }
    __syncthreads();

    // phase 2: last block scans the 98 block sums
    if (sflag) {
        __threadfence();
        int v2 = 0;
        if (t < 128) {
            v2 = (t < NBLK) ? g_bsum[t] : 0;
            sdata[t] = v2;
        }
        __syncthreads();
        for (int off = 1; off < 128; off <<= 1) {
            int u = (t >= off && t < 128) ? sdata[t - off] : 0;
            __syncthreads();
            if (t < 128) sdata[t] += u;
            __syncthreads();
        }
        if (t < NBLK) g_bpre[t] = sdata[t] - v2;
        if (t == (N_NODE >> 10)) {
            int bpre_here = sdata[t] - v2;
            g_rowtmp[N_NODE] = sdata[127] - bpre_here;
        }
    }
}

// ---------------------------------------------------------------------------
// K3: reorder edges into CSR slots + accumulate edge_agg (rank-based).
// ---------------------------------------------------------------------------
__global__ __launch_bounds__(256) void k_reorder(
    const int2*  __restrict__ edge_list,
    const float* __restrict__ edge_weight,
    const float* __restrict__ edge_feat)
{
    int e = blockIdx.x * blockDim.x + threadIdx.x;
    if (e >= N_EDGE) return;
    int2  nn = edge_list[e];
    float w  = edge_weight[e];
    int slot = g_rowtmp[nn.y] + g_bpre[nn.y >> 10] + g_rank[e];
    g_slot[slot] = make_int2(nn.x, __float_as_int(w));

    const float4* fr = (const float4*)(edge_feat + (size_t)e * DE);
    #pragma unroll
    for (int i = 0; i < DE / 4; i++) {
        float4 f = fr[i];
        f.x *= w; f.y *= w; f.z *= w; f.w *= w;
        red_add_v4(&g_eagg[(size_t)nn.y * (DE / 4) + i], f);
    }
}

// ---------------------------------------------------------------------------
// K4: gather-reduce.  One warp per node, edge loop unrolled x4 (fp16 cache).
// ---------------------------------------------------------------------------
__global__ __launch_bounds__(256) void k_gather(
    const float* __restrict__ x,
    const float* __restrict__ We,   // (16, 128)
    const float* __restrict__ be)   // (128,)
{
    const int node = blockIdx.x * 8 + (threadIdx.x >> 5);
    const int lane = threadIdx.x & 31;

    const float4* x4  = (const float4*)x;
    const float4* We4 = (const float4*)We;
    const float4* be4 = (const float4*)be;

    const int s = g_rowtmp[node]     + g_bpre[node >> 10];
    const int e = g_rowtmp[node + 1] + g_bpre[(node + 1) >> 10];

    float4 acc = make_float4(0.f, 0.f, 0.f, 0.f);

    int j = s;
    for (; j + 4 <= e; j += 4) {
        int2 s0 = g_slot[j + 0];
        int2 s1 = g_slot[j + 1];
        int2 s2 = g_slot[j + 2];
        int2 s3 = g_slot[j + 3];
        uint2 r0 = g_xh[(size_t)s0.x * 32 + lane];
        uint2 r1 = g_xh[(size_t)s1.x * 32 + lane];
        uint2 r2 = g_xh[(size_t)s2.x * 32 + lane];
        uint2 r3 = g_xh[(size_t)s3.x * 32 + lane];
        float4 v0 = h4_to_f4(r0);
        float4 v1 = h4_to_f4(r1);
        float4 v2 = h4_to_f4(r2);
        float4 v3 = h4_to_f4(r3);
        float w0 = __int_as_float(s0.y);
        float w1 = __int_as_float(s1.y);
        float w2 = __int_as_float(s2.y);
        float w3 = __int_as_float(s3.y);
        acc.x += w0 * v0.x + w1 * v1.x + w2 * v2.x + w3 * v3.x;
        acc.y += w0 * v0.y + w1 * v1.y + w2 * v2.y + w3 * v3.y;
        acc.z += w0 * v0.z + w1 * v1.z + w2 * v2.z + w3 * v3.z;
        acc.w += w0 * v0.w + w1 * v1.w + w2 * v2.w + w3 * v3.w;
    }
    for (; j < e; j++) {
        int2 sv = g_slot[j];
        float w = __int_as_float(sv.y);
        float4 v = h4_to_f4(g_xh[(size_t)sv.x * 32 + lane]);
        acc.x += w * v.x; acc.y += w * v.y;
        acc.z += w * v.z; acc.w += w * v.w;
    }

    // eagg @ W_edge: eagg row in lanes 0..3 (lane sl holds k = 4*sl + c)
    float4 ea = make_float4(0.f, 0.f, 0.f, 0.f);
    if (lane < (DE / 4)) ea = g_eagg[(size_t)node * (DE / 4) + lane];
    #pragma unroll
    for (int sl = 0; sl < 4; sl++) {
        float e0 = __shfl_sync(FULLM, ea.x, sl);
        float e1 = __shfl_sync(FULLM, ea.y, sl);
        float e2 = __shfl_sync(FULLM, ea.z, sl);
        float e3 = __shfl_sync(FULLM, ea.w, sl);
        float4 w0 = We4[(4 * sl + 0) * (D / 4) + lane];
        float4 w1 = We4[(4 * sl + 1) * (D / 4) + lane];
        float4 w2 = We4[(4 * sl + 2) * (D / 4) + lane];
        float4 w3 = We4[(4 * sl + 3) * (D / 4) + lane];
        acc.x += e0 * w0.x + e1 * w1.x + e2 * w2.x + e3 * w3.x;
        acc.y += e0 * w0.y + e1 * w1.y + e2 * w2.y + e3 * w3.y;
        acc.z += e0 * w0.z + e1 * w1.z + e2 * w2.z + e3 * w3.z;
        acc.w += e0 * w0.w + e1 * w1.w + e2 * w2.w + e3 * w3.w;
    }

    float4 xs = x4[(size_t)node * (D / 4) + lane];
    float4 bb = be4[lane];
    acc.x += xs.x + bb.x; acc.y += xs.y + bb.y;
    acc.z += xs.z + bb.z; acc.w += xs.w + bb.w;
    g_h[(size_t)node * (D / 4) + lane] = acc;
}

// ---------------------------------------------------------------------------
// K5: node MLP via tf32 tensor-core MMA (m16n8k8), fp32 accumulate.
// 64 nodes/block, 512 threads.  Warp w: 16 nodes (w&3) x 32 cols (w>>2).
// All smem arrays use stride 132 -> conflict-free fragment loads.
// ---------------------------------------------------------------------------
#define WS 132

__global__ __launch_bounds__(512, 1) void k_mlp(
    const float* __restrict__ W1,
    const float* __restrict__ b1,
    const float* __restrict__ W2,
    const float* __restrict__ b2,
    float* __restrict__ out)
{
    extern __shared__ float smem[];
    float* sW1 = smem;                 // 128 * 132 = 16896 floats
    float* sW2 = sW1 + 128 * WS;       // 16896 floats
    float* sh  = sW2 + 128 * WS;       // 64 * 132 = 8448 floats

    const int tid  = threadIdx.x;
    const int base = blockIdx.x * 64;

    // Stage weights + activations, tf32-rounded at store time
    {
        const float4* W1v = (const float4*)W1;
        const float4* W2v = (const float4*)W2;
        for (int i = tid; i < 4096; i += 512) {
            int k = i >> 5, c4 = (i & 31) * 4;
            float4 a = W1v[i];
            uint4 ra = make_uint4(f2tf(a.x), f2tf(a.y), f2tf(a.z), f2tf(a.w));
            *(uint4*)(sW1 + k * WS + c4) = ra;
            float4 b = W2v[i];
            uint4 rb = make_uint4(f2tf(b.x), f2tf(b.y), f2tf(b.z), f2tf(b.w));
            *(uint4*)(sW2 + k * WS + c4) = rb;
        }
        for (int i = tid; i < 64 * 32; i += 512) {
            int n = i >> 5, c4 = (i & 31) * 4;
            float4 v = g_h[(size_t)(base + n) * 32 + (i & 31)];
            uint4 rv = make_uint4(f2tf(v.x), f2tf(v.y), f2tf(v.z), f2tf(v.w));
            *(uint4*)(sh + n * WS + c4) = rv;
        }
    }
    __syncthreads();

    const int lane  = tid & 31;
    const int warp  = tid >> 5;
    const int gid   = lane >> 2;    // 0..7
    const int tig   = lane & 3;     // 0..3
    const int nbase = (warp & 3) * 16;
    const int cbase = (warp >> 2) * 32;

    const unsigned* ush = (const unsigned*)sh;
    const unsigned* uw1 = (const unsigned*)sW1;
    const unsigned* uw2 = (const unsigned*)sW2;

    float c[4][4];

    // ---- Layer 1 ----
    #pragma unroll
    for (int ct = 0; ct < 4; ct++) {
        int col0 = cbase + ct * 8 + 2 * tig;
        float2 bb = *(const float2*)(b1 + col0);
        c[ct][0] = bb.x; c[ct][1] = bb.y; c[ct][2] = bb.x; c[ct][3] = bb.y;
    }
    #pragma unroll 4
    for (int k0 = 0; k0 < 128; k0 += 8) {
        unsigned a0 = ush[(nbase + gid)     * WS + k0 + tig];
        unsigned a1 = ush[(nbase + gid + 8) * WS + k0 + tig];
        unsigned a2 = ush[(nbase + gid)     * WS + k0 + tig + 4];
        unsigned a3 = ush[(nbase + gid + 8) * WS + k0 + tig + 4];
        #pragma unroll
        for (int ct = 0; ct < 4; ct++) {
            int cc = cbase + ct * 8 + gid;
            unsigned bb0 = uw1[(k0 + tig)     * WS + cc];
            unsigned bb1 = uw1[(k0 + tig + 4) * WS + cc];
            mma_tf32(c[ct][0], c[ct][1], c[ct][2], c[ct][3],
                     a0, a1, a2, a3, bb0, bb1);
        }
    }
    __syncthreads();   // all layer-1 A reads done before sh overwrite

    // ReLU + tf32 round + write h1 back to sh
    {
        unsigned* wsh = (unsigned*)sh;
        #pragma unroll
        for (int ct = 0; ct < 4; ct++) {
            int col0 = cbase + ct * 8 + 2 * tig;
            unsigned t0 = f2tf(fmaxf(c[ct][0], 0.f));
            unsigned t1 = f2tf(fmaxf(c[ct][1], 0.f));
            unsigned t2 = f2tf(fmaxf(c[ct][2], 0.f));
            unsigned t3 = f2tf(fmaxf(c[ct][3], 0.f));
            *(uint2*)(wsh + (nbase + gid)     * WS + col0) = make_uint2(t0, t1);
            *(uint2*)(wsh + (nbase + gid + 8) * WS + col0) = make_uint2(t2, t3);
        }
    }
    __syncthreads();

    // ---- Layer 2 ----
    #pragma unroll
    for (int ct = 0; ct < 4; ct++) {
        int col0 = cbase + ct * 8 + 2 * tig;
        float2 bb = *(const float2*)(b2 + col0);
        c[ct][0] = bb.x; c[ct][1] = bb.y; c[ct][2] = bb.x; c[ct][3] = bb.y;
    }
    #pragma unroll 4
    for (int k0 = 0; k0 < 128; k0 += 8) {
        unsigned a0 = ush[(nbase + gid)     * WS + k0 + tig];
        unsigned a1 = ush[(nbase + gid + 8) * WS + k0 + tig];
        unsigned a2 = ush[(nbase + gid)     * WS + k0 + tig + 4];
        unsigned a3 = ush[(nbase + gid + 8) * WS + k0 + tig + 4];
        #pragma unroll
        for (int ct = 0; ct < 4; ct++) {
            int cc = cbase + ct * 8 + gid;
            unsigned bb0 = uw2[(k0 + tig)     * WS + cc];
            unsigned bb1 = uw2[(k0 + tig + 4) * WS + cc];
            mma_tf32(c[ct][0], c[ct][1], c[ct][2], c[ct][3],
                     a0, a1, a2, a3, bb0, bb1);
        }
    }

    // Final ReLU + global store (float2 per fragment row)
    {
        int node0 = base + nbase + gid;
        int node1 = node0 + 8;
        #pragma unroll
        for (int ct = 0; ct < 4; ct++) {
            int col0 = cbase + ct * 8 + 2 * tig;
            if (node0 < N_NODE) {
                float2 r0 = make_float2(fmaxf(c[ct][0], 0.f), fmaxf(c[ct][1], 0.f));
                *(float2*)(out + (size_t)node0 * D + col0) = r0;
            }
            if (node1 < N_NODE) {
                float2 r1 = make_float2(fmaxf(c[ct][2], 0.f), fmaxf(c[ct][3], 0.f));
                *(float2*)(out + (size_t)node1 * D + col0) = r1;
            }
        }
    }
}

// ---------------------------------------------------------------------------
// Launch
// ---------------------------------------------------------------------------
extern "C" void kernel_launch(void* const* d_in, const int* in_sizes, int n_in,
                              void* d_out, int out_size)
{
    const int2*  edge_list   = (const int2*)d_in[0];
    const float* edge_weight = (const float*)d_in[1];
    const float* edge_feat   = (const float*)d_in[2];
    // d_in[3] = num_node (constant)
    const float* x  = (const float*)d_in[4];
    const float* We = (const float*)d_in[5];
    const float* be = (const float*)d_in[6];
    const float* W1 = (const float*)d_in[7];
    const float* b1 = (const float*)d_in[8];
    const float* W2 = (const float*)d_in[9];
    const float* b2 = (const float*)d_in[10];
    float* out = (float*)d_out;

    const int smem_bytes = (128 * WS * 2 + 64 * WS) * 4;   // 168960 B
    cudaFuncSetAttribute(k_mlp, cudaFuncAttributeMaxDynamicSharedMemorySize, smem_bytes);

    void* p_cnt  = nullptr;
    void* p_done = nullptr;
    cudaGetSymbolAddress(&p_cnt,  g_cnt);
    cudaGetSymbolAddress(&p_done, g_done);
    cudaMemsetAsync(p_cnt,  0, sizeof(int) * N_NODE);
    cudaMemsetAsync(p_done, 0, sizeof(int));

    k_hist<<<(N_EDGE + 255) / 256, 256>>>(edge_list);
    k_scan<<<NBLK, 1024>>>((const float4*)x);
    k_reorder<<<(N_EDGE + 255) / 256, 256>>>(edge_list, edge_weight, edge_feat);
    k_gather<<<N_NODE / 8, 256>>>(x, We, be);
    k_mlp<<<(N_NODE + 63) / 64, 512, smem_bytes>>>(W1, b1, W2, b2, out);
}

// round 16
// speedup vs baseline: 1.5078x; 1.0873x over previous
#include <cuda_runtime.h>
#include <cuda_bf16.h>
#include <cuda_fp16.h>
#include <cstdint>

#define N_NODE 100000
#define N_EDGE 1600000
#define D      128
#define DE     16
#define FULLM  0xFFFFFFFFu
#define NBLK   98          // ceil(N_NODE / 1024)
#define WS     132         // padded stride (floats) for all MMA smem tiles

// ---------------------------------------------------------------------------
// Scratch (static device arrays; allocation is forbidden)
// ---------------------------------------------------------------------------
__device__ int      g_cnt[N_NODE];
__device__ int      g_rank[N_EDGE];           // per-edge insertion rank
__device__ int      g_rowtmp[N_NODE + 1];     // block-local exclusive prefix
__device__ int      g_bsum[NBLK];
__device__ int      g_bpre[NBLK];
__device__ int      g_done;                   // scan completion counter
__device__ int2     g_slot[N_EDGE];           // (src_node, weight_bits)
__device__ float4   g_eagg[N_NODE * (DE / 4)];// 6.4 MB
__device__ uint2    g_xh[N_NODE * 32];        // x in fp16: 256B/row, 25.6MB
__device__ float4   g_h[(N_NODE + 64) * (D / 4)]; // pre-MLP activations (tf32-rounded)
__device__ unsigned g_w1t[D * WS];            // W1 tf32, col-major [c][k], stride WS
__device__ unsigned g_w2t[D * WS];            // W2 tf32, col-major [c][k], stride WS

// ---------------------------------------------------------------------------
// helpers
// ---------------------------------------------------------------------------
__device__ __forceinline__ void red_add_v4(float4* addr, float4 v)
{
    asm volatile("red.global.add.v4.f32 [%0], {%1, %2, %3, %4};"
                 :: "l"(addr), "f"(v.x), "f"(v.y), "f"(v.z), "f"(v.w)
                 : "memory");
}
__device__ __forceinline__ float4 h4_to_f4(uint2 r)
{
    __half2 h0 = *reinterpret_cast<__half2*>(&r.x);
    __half2 h1 = *reinterpret_cast<__half2*>(&r.y);
    float2 a = __half22float2(h0);
    float2 b = __half22float2(h1);
    return make_float4(a.x, a.y, b.x, b.y);
}
__device__ __forceinline__ unsigned f2tf(float f)
{
    unsigned r;
    asm("cvt.rna.tf32.f32 %0, %1;" : "=r"(r) : "f"(f));
    return r;
}
__device__ __forceinline__ void mma_tf32(
    float& d0, float& d1, float& d2, float& d3,
    unsigned a0, unsigned a1, unsigned a2, unsigned a3,
    unsigned b0, unsigned b1)
{
    asm("mma.sync.aligned.m16n8k8.row.col.f32.tf32.tf32.f32 "
        "{%0,%1,%2,%3},{%4,%5,%6,%7},{%8,%9},{%0,%1,%2,%3};"
        : "+f"(d0), "+f"(d1), "+f"(d2), "+f"(d3)
        : "r"(a0), "r"(a1), "r"(a2), "r"(a3), "r"(b0), "r"(b1));
}

// ---------------------------------------------------------------------------
// K1: histogram of destination nodes + per-edge rank
// ---------------------------------------------------------------------------
__global__ __launch_bounds__(256) void k_hist(const int2* __restrict__ edge_list)
{
    int e = blockIdx.x * blockDim.x + threadIdx.x;
    if (e < N_EDGE)
        g_rank[e] = atomicAdd(&g_cnt[edge_list[e].y], 1);
}

// ---------------------------------------------------------------------------
// K2: merged scan + fp16 conversion of x + tf32/transpose of W1,W2 + eagg zero.
// 98 blocks <= 148 SMs, last-block-done pattern.
// ---------------------------------------------------------------------------
__global__ __launch_bounds__(1024) void k_scan(
    const float4* __restrict__ x4,
    const float*  __restrict__ W1,
    const float*  __restrict__ W2)
{
    __shared__ int sdata[1024];
    __shared__ int sflag;
    const int t = threadIdx.x, b = blockIdx.x;
    const int idx = b * 1024 + t;
    const int gsz = NBLK * 1024;

    // phase 0a: convert x -> fp16 (coalesced grid-stride)
    for (int i = idx; i < N_NODE * 32; i += gsz) {
        float4 v = x4[i];
        __half2 h0 = __floats2half2_rn(v.x, v.y);
        __half2 h1 = __floats2half2_rn(v.z, v.w);
        uint2 r;
        r.x = *reinterpret_cast<uint32_t*>(&h0);
        r.y = *reinterpret_cast<uint32_t*>(&h1);
        g_xh[i] = r;
    }
    // phase 0b: tf32-round + transpose weights into col-major scratch
    for (int i = idx; i < D * D; i += gsz) {
        int k = i & (D - 1), c = i >> 7;
        g_w1t[c * WS + k] = f2tf(W1[k * D + c]);
        g_w2t[c * WS + k] = f2tf(W2[k * D + c]);
    }
    // phase 0c: zero eagg
    if (idx < N_NODE) {
        const float4 z = make_float4(0.f, 0.f, 0.f, 0.f);
        float4* ez = &g_eagg[(size_t)idx * (DE / 4)];
        ez[0] = z; ez[1] = z; ez[2] = z; ez[3] = z;
    }

    // phase 1: block-local exclusive scan of g_cnt
    int v = (idx < N_NODE) ? g_cnt[idx] : 0;
    sdata[t] = v;
    __syncthreads();
    for (int off = 1; off < 1024; off <<= 1) {
        int u = (t >= off) ? sdata[t - off] : 0;
        __syncthreads();
        sdata[t] += u;
        __syncthreads();
    }
    if (idx < N_NODE) g_rowtmp[idx] = sdata[t] - v;

    if (t == 1023) {
        g_bsum[b] = sdata[1023];
        __threadfence();
        int old = atomicAdd(&g_done, 1);
        sflag = (old == NBLK - 1) ? 1 : 0;
    }
    __syncthreads();

    // phase 2: last block scans the 98 block sums
    if (sflag) {
        __threadfence();
        int v2 = 0;
        if (t < 128) {
            v2 = (t < NBLK) ? g_bsum[t] : 0;
            sdata[t] = v2;
        }
        __syncthreads();
        for (int off = 1; off < 128; off <<= 1) {
            int u = (t >= off && t < 128) ? sdata[t - off] : 0;
            __syncthreads();
            if (t < 128) sdata[t] += u;
            __syncthreads();
        }
        if (t < NBLK) g_bpre[t] = sdata[t] - v2;
        if (t == (N_NODE >> 10)) {
            int bpre_here = sdata[t] - v2;
            g_rowtmp[N_NODE] = sdata[127] - bpre_here;
        }
    }
}

// ---------------------------------------------------------------------------
// K3: reorder edges into CSR slots + accumulate edge_agg (rank-based).
// ---------------------------------------------------------------------------
__global__ __launch_bounds__(256) void k_reorder(
    const int2*  __restrict__ edge_list,
    const float* __restrict__ edge_weight,
    const float* __restrict__ edge_feat)
{
    int e = blockIdx.x * blockDim.x + threadIdx.x;
    if (e >= N_EDGE) return;
    int2  nn = edge_list[e];
    float w  = edge_weight[e];
    int slot = g_rowtmp[nn.y] + g_bpre[nn.y >> 10] + g_rank[e];
    g_slot[slot] = make_int2(nn.x, __float_as_int(w));

    const float4* fr = (const float4*)(edge_feat + (size_t)e * DE);
    #pragma unroll
    for (int i = 0; i < DE / 4; i++) {
        float4 f = fr[i];
        f.x *= w; f.y *= w; f.z *= w; f.w *= w;
        red_add_v4(&g_eagg[(size_t)nn.y * (DE / 4) + i], f);
    }
}

// ---------------------------------------------------------------------------
// K4: gather-reduce.  One warp per node, edge loop unrolled x4 (fp16 cache).
// h written pre-rounded to tf32 (same rounding point as R15 staging).
// ---------------------------------------------------------------------------
__global__ __launch_bounds__(256) void k_gather(
    const float* __restrict__ x,
    const float* __restrict__ We,   // (16, 128)
    const float* __restrict__ be)   // (128,)
{
    const int node = blockIdx.x * 8 + (threadIdx.x >> 5);
    const int lane = threadIdx.x & 31;

    const float4* x4  = (const float4*)x;
    const float4* We4 = (const float4*)We;
    const float4* be4 = (const float4*)be;

    const int s = g_rowtmp[node]     + g_bpre[node >> 10];
    const int e = g_rowtmp[node + 1] + g_bpre[(node + 1) >> 10];

    float4 acc = make_float4(0.f, 0.f, 0.f, 0.f);

    int j = s;
    for (; j + 4 <= e; j += 4) {
        int2 s0 = g_slot[j + 0];
        int2 s1 = g_slot[j + 1];
        int2 s2 = g_slot[j + 2];
        int2 s3 = g_slot[j + 3];
        uint2 r0 = g_xh[(size_t)s0.x * 32 + lane];
        uint2 r1 = g_xh[(size_t)s1.x * 32 + lane];
        uint2 r2 = g_xh[(size_t)s2.x * 32 + lane];
        uint2 r3 = g_xh[(size_t)s3.x * 32 + lane];
        float4 v0 = h4_to_f4(r0);
        float4 v1 = h4_to_f4(r1);
        float4 v2 = h4_to_f4(r2);
        float4 v3 = h4_to_f4(r3);
        float w0 = __int_as_float(s0.y);
        float w1 = __int_as_float(s1.y);
        float w2 = __int_as_float(s2.y);
        float w3 = __int_as_float(s3.y);
        acc.x += w0 * v0.x + w1 * v1.x + w2 * v2.x + w3 * v3.x;
        acc.y += w0 * v0.y + w1 * v1.y + w2 * v2.y + w3 * v3.y;
        acc.z += w0 * v0.z + w1 * v1.z + w2 * v2.z + w3 * v3.z;
        acc.w += w0 * v0.w + w1 * v1.w + w2 * v2.w + w3 * v3.w;
    }
    for (; j < e; j++) {
        int2 sv = g_slot[j];
        float w = __int_as_float(sv.y);
        float4 v = h4_to_f4(g_xh[(size_t)sv.x * 32 + lane]);
        acc.x += w * v.x; acc.y += w * v.y;
        acc.z += w * v.z; acc.w += w * v.w;
    }

    // eagg @ W_edge: eagg row in lanes 0..3 (lane sl holds k = 4*sl + c)
    float4 ea = make_float4(0.f, 0.f, 0.f, 0.f);
    if (lane < (DE / 4)) ea = g_eagg[(size_t)node * (DE / 4) + lane];
    #pragma unroll
    for (int sl = 0; sl < 4; sl++) {
        float e0 = __shfl_sync(FULLM, ea.x, sl);
        float e1 = __shfl_sync(FULLM, ea.y, sl);
        float e2 = __shfl_sync(FULLM, ea.z, sl);
        float e3 = __shfl_sync(FULLM, ea.w, sl);
        float4 w0 = We4[(4 * sl + 0) * (D / 4) + lane];
        float4 w1 = We4[(4 * sl + 1) * (D / 4) + lane];
        float4 w2 = We4[(4 * sl + 2) * (D / 4) + lane];
        float4 w3 = We4[(4 * sl + 3) * (D / 4) + lane];
        acc.x += e0 * w0.x + e1 * w1.x + e2 * w2.x + e3 * w3.x;
        acc.y += e0 * w0.y + e1 * w1.y + e2 * w2.y + e3 * w3.y;
        acc.z += e0 * w0.z + e1 * w1.z + e2 * w2.z + e3 * w3.z;
        acc.w += e0 * w0.w + e1 * w1.w + e2 * w2.w + e3 * w3.w;
    }

    float4 xs = x4[(size_t)node * (D / 4) + lane];
    float4 bb = be4[lane];
    acc.x += xs.x + bb.x; acc.y += xs.y + bb.y;
    acc.z += xs.z + bb.z; acc.w += xs.w + bb.w;

    // tf32-round h here (rounding point identical to R15's staging)
    float4 ht;
    ht.x = __uint_as_float(f2tf(acc.x));
    ht.y = __uint_as_float(f2tf(acc.y));
    ht.z = __uint_as_float(f2tf(acc.z));
    ht.w = __uint_as_float(f2tf(acc.w));
    g_h[(size_t)node * (D / 4) + lane] = ht;
}

// ---------------------------------------------------------------------------
// K5: node MLP via tf32 MMA (m16n8k8), fp32 accumulate.
// Weights pre-converted col-major [c][k] -> staging is a plain copy and
// B-fragment loads are conflict-free (bank = (4*gid+tig)%32).
// 64 nodes/block, 512 threads.  Warp w: 16 nodes (w&3) x 32 cols (w>>2).
// ---------------------------------------------------------------------------
__global__ __launch_bounds__(512, 1) void k_mlp(
    const float* __restrict__ b1,
    const float* __restrict__ b2,
    float* __restrict__ out)
{
    extern __shared__ float smem[];
    float* sW1 = smem;                 // 128 * 132 floats, col-major [c][k]
    float* sW2 = sW1 + D * WS;
    float* sh  = sW2 + D * WS;         // 64 * 132 floats, row-major [n][k]

    const int tid  = threadIdx.x;
    const int base = blockIdx.x * 64;

    // Stage: pure copies (weights already tf32 + transposed; h already tf32)
    {
        const uint4* w1v = (const uint4*)g_w1t;
        const uint4* w2v = (const uint4*)g_w2t;
        for (int i = tid; i < 4096; i += 512) {
            int c = i >> 5, k4 = i & 31;
            *(uint4*)(sW1 + c * WS + k4 * 4) = w1v[(c * WS) / 4 + k4];
            *(uint4*)(sW2 + c * WS + k4 * 4) = w2v[(c * WS) / 4 + k4];
        }
        for (int i = tid; i < 64 * 32; i += 512) {
            int n = i >> 5, c4 = i & 31;
            *(float4*)(sh + n * WS + c4 * 4) = g_h[(size_t)(base + n) * 32 + c4];
        }
    }
    __syncthreads();

    const int lane  = tid & 31;
    const int warp  = tid >> 5;
    const int gid   = lane >> 2;    // 0..7
    const int tig   = lane & 3;     // 0..3
    const int nbase = (warp & 3) * 16;
    const int cbase = (warp >> 2) * 32;

    const unsigned* ush = (const unsigned*)sh;
    const unsigned* uw1 = (const unsigned*)sW1;
    const unsigned* uw2 = (const unsigned*)sW2;

    float c[4][4];

    // ---- Layer 1 ----
    #pragma unroll
    for (int ct = 0; ct < 4; ct++) {
        int col0 = cbase + ct * 8 + 2 * tig;
        float2 bb = *(const float2*)(b1 + col0);
        c[ct][0] = bb.x; c[ct][1] = bb.y; c[ct][2] = bb.x; c[ct][3] = bb.y;
    }
    #pragma unroll 4
    for (int k0 = 0; k0 < 128; k0 += 8) {
        unsigned a0 = ush[(nbase + gid)     * WS + k0 + tig];
        unsigned a1 = ush[(nbase + gid + 8) * WS + k0 + tig];
        unsigned a2 = ush[(nbase + gid)     * WS + k0 + tig + 4];
        unsigned a3 = ush[(nbase + gid + 8) * WS + k0 + tig + 4];
        #pragma unroll
        for (int ct = 0; ct < 4; ct++) {
            int cc = cbase + ct * 8 + gid;
            unsigned bb0 = uw1[cc * WS + k0 + tig];
            unsigned bb1 = uw1[cc * WS + k0 + tig + 4];
            mma_tf32(c[ct][0], c[ct][1], c[ct][2], c[ct][3],
                     a0, a1, a2, a3, bb0, bb1);
        }
    }
    __syncthreads();   // all layer-1 A reads done before sh overwrite

    // ReLU + tf32 round + write h1 back to sh
    {
        unsigned* wsh = (unsigned*)sh;
        #pragma unroll
        for (int ct = 0; ct < 4; ct++) {
            int col0 = cbase + ct * 8 + 2 * tig;
            unsigned t0 = f2tf(fmaxf(c[ct][0], 0.f));
            unsigned t1 = f2tf(fmaxf(c[ct][1], 0.f));
            unsigned t2 = f2tf(fmaxf(c[ct][2], 0.f));
            unsigned t3 = f2tf(fmaxf(c[ct][3], 0.f));
            *(uint2*)(wsh + (nbase + gid)     * WS + col0) = make_uint2(t0, t1);
            *(uint2*)(wsh + (nbase + gid + 8) * WS + col0) = make_uint2(t2, t3);
        }
    }
    __syncthreads();

    // ---- Layer 2 ----
    #pragma unroll
    for (int ct = 0; ct < 4; ct++) {
        int col0 = cbase + ct * 8 + 2 * tig;
        float2 bb = *(const float2*)(b2 + col0);
        c[ct][0] = bb.x; c[ct][1] = bb.y; c[ct][2] = bb.x; c[ct][3] = bb.y;
    }
    #pragma unroll 4
    for (int k0 = 0; k0 < 128; k0 += 8) {
        unsigned a0 = ush[(nbase + gid)     * WS + k0 + tig];
        unsigned a1 = ush[(nbase + gid + 8) * WS + k0 + tig];
        unsigned a2 = ush[(nbase + gid)     * WS + k0 + tig + 4];
        unsigned a3 = ush[(nbase + gid + 8) * WS + k0 + tig + 4];
        #pragma unroll
        for (int ct = 0; ct < 4; ct++) {
            int cc = cbase + ct * 8 + gid;
            unsigned bb0 = uw2[cc * WS + k0 + tig];
            unsigned bb1 = uw2[cc * WS + k0 + tig + 4];
            mma_tf32(c[ct][0], c[ct][1], c[ct][2], c[ct][3],
                     a0, a1, a2, a3, bb0, bb1);
        }
    }

    // Final ReLU + global store (float2 per fragment row)
    {
        int node0 = base + nbase + gid;
        int node1 = node0 + 8;
        #pragma unroll
        for (int ct = 0; ct < 4; ct++) {
            int col0 = cbase + ct * 8 + 2 * tig;
            if (node0 < N_NODE) {
                float2 r0 = make_float2(fmaxf(c[ct][0], 0.f), fmaxf(c[ct][1], 0.f));
                *(float2*)(out + (size_t)node0 * D + col0) = r0;
            }
            if (node1 < N_NODE) {
                float2 r1 = make_float2(fmaxf(c[ct][2], 0.f), fmaxf(c[ct][3], 0.f));
                *(float2*)(out + (size_t)node1 * D + col0) = r1;
            }
        }
    }
}

// ---------------------------------------------------------------------------
// Launch
// ---------------------------------------------------------------------------
extern "C" void kernel_launch(void* const* d_in, const int* in_sizes, int n_in,
                              void* d_out, int out_size)
{
    const int2*  edge_list   = (const int2*)d_in[0];
    const float* edge_weight = (const float*)d_in[1];
    const float* edge_feat   = (const float*)d_in[2];
    // d_in[3] = num_node (constant)
    const float* x  = (const float*)d_in[4];
    const float* We = (const float*)d_in[5];
    const float* be = (const float*)d_in[6];
    const float* W1 = (const float*)d_in[7];
    const float* b1 = (const float*)d_in[8];
    const float* W2 = (const float*)d_in[9];
    const float* b2 = (const float*)d_in[10];
    float* out = (float*)d_out;

    const int smem_bytes = (D * WS * 2 + 64 * WS) * 4;   // 168960 B
    cudaFuncSetAttribute(k_mlp, cudaFuncAttributeMaxDynamicSharedMemorySize, smem_bytes);

    void* p_cnt  = nullptr;
    void* p_done = nullptr;
    cudaGetSymbolAddress(&p_cnt,  g_cnt);
    cudaGetSymbolAddress(&p_done, g_done);
    cudaMemsetAsync(p_cnt,  0, sizeof(int) * N_NODE);
    cudaMemsetAsync(p_done, 0, sizeof(int));

    k_hist<<<(N_EDGE + 255) / 256, 256>>>(edge_list);
    k_scan<<<NBLK, 1024>>>((const float4*)x, W1, W2);
    k_reorder<<<(N_EDGE + 255) / 256, 256>>>(edge_list, edge_weight, edge_feat);
    k_gather<<<N_NODE / 8, 256>>>(x, We, be);
    k_mlp<<<(N_NODE + 63) / 64, 512, smem_bytes>>>(b1, b2, out);
}

// round 17
// speedup vs baseline: 1.5750x; 1.0446x over previous
#include <cuda_runtime.h>
#include <cuda_bf16.h>
#include <cuda_fp16.h>
#include <cstdint>

#define N_NODE 100000
#define N_EDGE 1600000
#define D      128
#define DE     16
#define FULLM  0xFFFFFFFFu
#define NBLK   98          // ceil(N_NODE / 1024)
#define WS     132         // padded stride (floats) for all MMA smem tiles
#define MLP_N  128         // nodes per MLP block

// ---------------------------------------------------------------------------
// Scratch (static device arrays; allocation is forbidden)
// ---------------------------------------------------------------------------
__device__ int      g_cnt[N_NODE];
__device__ int      g_rank[N_EDGE];           // per-edge insertion rank
__device__ int      g_rowtmp[N_NODE + 1];     // block-local exclusive prefix
__device__ int      g_bsum[NBLK];
__device__ int      g_bpre[NBLK];
__device__ int      g_done;                   // scan completion counter
__device__ int2     g_slot[N_EDGE];           // (src_node, weight_bits)
__device__ float4   g_eagg[N_NODE * (DE / 4)];// 6.4 MB
__device__ uint2    g_xh[N_NODE * 32];        // x in fp16: 256B/row, 25.6MB
__device__ float4   g_h[(N_NODE + MLP_N) * (D / 4)]; // pre-MLP activations (tf32-rounded)
__device__ unsigned g_w1t[D * WS];            // W1 tf32, col-major [c][k], stride WS
__device__ unsigned g_w2t[D * WS];            // W2 tf32, col-major [c][k], stride WS

// ---------------------------------------------------------------------------
// helpers
// ---------------------------------------------------------------------------
__device__ __forceinline__ void red_add_v4(float4* addr, float4 v)
{
    asm volatile("red.global.add.v4.f32 [%0], {%1, %2, %3, %4};"
                 :: "l"(addr), "f"(v.x), "f"(v.y), "f"(v.z), "f"(v.w)
                 : "memory");
}
__device__ __forceinline__ float4 h4_to_f4(uint2 r)
{
    __half2 h0 = *reinterpret_cast<__half2*>(&r.x);
    __half2 h1 = *reinterpret_cast<__half2*>(&r.y);
    float2 a = __half22float2(h0);
    float2 b = __half22float2(h1);
    return make_float4(a.x, a.y, b.x, b.y);
}
__device__ __forceinline__ unsigned f2tf(float f)
{
    unsigned r;
    asm("cvt.rna.tf32.f32 %0, %1;" : "=r"(r) : "f"(f));
    return r;
}
__device__ __forceinline__ void mma_tf32(
    float& d0, float& d1, float& d2, float& d3,
    unsigned a0, unsigned a1, unsigned a2, unsigned a3,
    unsigned b0, unsigned b1)
{
    asm("mma.sync.aligned.m16n8k8.row.col.f32.tf32.tf32.f32 "
        "{%0,%1,%2,%3},{%4,%5,%6,%7},{%8,%9},{%0,%1,%2,%3};"
        : "+f"(d0), "+f"(d1), "+f"(d2), "+f"(d3)
        : "r"(a0), "r"(a1), "r"(a2), "r"(a3), "r"(b0), "r"(b1));
}

// ---------------------------------------------------------------------------
// K1: histogram of destination nodes + per-edge rank
// ---------------------------------------------------------------------------
__global__ __launch_bounds__(256) void k_hist(const int2* __restrict__ edge_list)
{
    int e = blockIdx.x * blockDim.x + threadIdx.x;
    if (e < N_EDGE)
        g_rank[e] = atomicAdd(&g_cnt[edge_list[e].y], 1);
}

// ---------------------------------------------------------------------------
// K2: merged scan + fp16 conversion of x + tf32/transpose of W1,W2 + eagg zero.
// ---------------------------------------------------------------------------
__global__ __launch_bounds__(1024) void k_scan(
    const float4* __restrict__ x4,
    const float*  __restrict__ W1,
    const float*  __restrict__ W2)
{
    __shared__ int sdata[1024];
    __shared__ int sflag;
    const int t = threadIdx.x, b = blockIdx.x;
    const int idx = b * 1024 + t;
    const int gsz = NBLK * 1024;

    // phase 0a: convert x -> fp16 (coalesced grid-stride)
    for (int i = idx; i < N_NODE * 32; i += gsz) {
        float4 v = x4[i];
        __half2 h0 = __floats2half2_rn(v.x, v.y);
        __half2 h1 = __floats2half2_rn(v.z, v.w);
        uint2 r;
        r.x = *reinterpret_cast<uint32_t*>(&h0);
        r.y = *reinterpret_cast<uint32_t*>(&h1);
        g_xh[i] = r;
    }
    // phase 0b: tf32-round + transpose weights into col-major scratch
    for (int i = idx; i < D * D; i += gsz) {
        int k = i & (D - 1), c = i >> 7;
        g_w1t[c * WS + k] = f2tf(W1[k * D + c]);
        g_w2t[c * WS + k] = f2tf(W2[k * D + c]);
    }
    // phase 0c: zero eagg
    if (idx < N_NODE) {
        const float4 z = make_float4(0.f, 0.f, 0.f, 0.f);
        float4* ez = &g_eagg[(size_t)idx * (DE / 4)];
        ez[0] = z; ez[1] = z; ez[2] = z; ez[3] = z;
    }

    // phase 1: block-local exclusive scan of g_cnt
    int v = (idx < N_NODE) ? g_cnt[idx] : 0;
    sdata[t] = v;
    __syncthreads();
    for (int off = 1; off < 1024; off <<= 1) {
        int u = (t >= off) ? sdata[t - off] : 0;
        __syncthreads();
        sdata[t] += u;
        __syncthreads();
    }
    if (idx < N_NODE) g_rowtmp[idx] = sdata[t] - v;

    if (t == 1023) {
        g_bsum[b] = sdata[1023];
        __threadfence();
        int old = atomicAdd(&g_done, 1);
        sflag = (old == NBLK - 1) ? 1 : 0;
    }
    __syncthreads();

    // phase 2: last block scans the 98 block sums
    if (sflag) {
        __threadfence();
        int v2 = 0;
        if (t < 128) {
            v2 = (t < NBLK) ? g_bsum[t] : 0;
            sdata[t] = v2;
        }
        __syncthreads();
        for (int off = 1; off < 128; off <<= 1) {
            int u = (t >= off && t < 128) ? sdata[t - off] : 0;
            __syncthreads();
            if (t < 128) sdata[t] += u;
            __syncthreads();
        }
        if (t < NBLK) g_bpre[t] = sdata[t] - v2;
        if (t == (N_NODE >> 10)) {
            int bpre_here = sdata[t] - v2;
            g_rowtmp[N_NODE] = sdata[127] - bpre_here;
        }
    }
}

// ---------------------------------------------------------------------------
// K3: reorder edges into CSR slots + accumulate edge_agg (rank-based).
// ---------------------------------------------------------------------------
__global__ __launch_bounds__(256) void k_reorder(
    const int2*  __restrict__ edge_list,
    const float* __restrict__ edge_weight,
    const float* __restrict__ edge_feat)
{
    int e = blockIdx.x * blockDim.x + threadIdx.x;
    if (e >= N_EDGE) return;
    int2  nn = edge_list[e];
    float w  = edge_weight[e];
    int slot = g_rowtmp[nn.y] + g_bpre[nn.y >> 10] + g_rank[e];
    g_slot[slot] = make_int2(nn.x, __float_as_int(w));

    const float4* fr = (const float4*)(edge_feat + (size_t)e * DE);
    #pragma unroll
    for (int i = 0; i < DE / 4; i++) {
        float4 f = fr[i];
        f.x *= w; f.y *= w; f.z *= w; f.w *= w;
        red_add_v4(&g_eagg[(size_t)nn.y * (DE / 4) + i], f);
    }
}

// ---------------------------------------------------------------------------
// K4: gather-reduce.  One warp per node, edge loop unrolled x4 (fp16 cache).
// h written pre-rounded to tf32.
// ---------------------------------------------------------------------------
__global__ __launch_bounds__(256) void k_gather(
    const float* __restrict__ x,
    const float* __restrict__ We,   // (16, 128)
    const float* __restrict__ be)   // (128,)
{
    const int node = blockIdx.x * 8 + (threadIdx.x >> 5);
    const int lane = threadIdx.x & 31;

    const float4* x4  = (const float4*)x;
    const float4* We4 = (const float4*)We;
    const float4* be4 = (const float4*)be;

    const int s = g_rowtmp[node]     + g_bpre[node >> 10];
    const int e = g_rowtmp[node + 1] + g_bpre[(node + 1) >> 10];

    float4 acc = make_float4(0.f, 0.f, 0.f, 0.f);

    int j = s;
    for (; j + 4 <= e; j += 4) {
        int2 s0 = g_slot[j + 0];
        int2 s1 = g_slot[j + 1];
        int2 s2 = g_slot[j + 2];
        int2 s3 = g_slot[j + 3];
        uint2 r0 = g_xh[(size_t)s0.x * 32 + lane];
        uint2 r1 = g_xh[(size_t)s1.x * 32 + lane];
        uint2 r2 = g_xh[(size_t)s2.x * 32 + lane];
        uint2 r3 = g_xh[(size_t)s3.x * 32 + lane];
        float4 v0 = h4_to_f4(r0);
        float4 v1 = h4_to_f4(r1);
        float4 v2 = h4_to_f4(r2);
        float4 v3 = h4_to_f4(r3);
        float w0 = __int_as_float(s0.y);
        float w1 = __int_as_float(s1.y);
        float w2 = __int_as_float(s2.y);
        float w3 = __int_as_float(s3.y);
        acc.x += w0 * v0.x + w1 * v1.x + w2 * v2.x + w3 * v3.x;
        acc.y += w0 * v0.y + w1 * v1.y + w2 * v2.y + w3 * v3.y;
        acc.z += w0 * v0.z + w1 * v1.z + w2 * v2.z + w3 * v3.z;
        acc.w += w0 * v0.w + w1 * v1.w + w2 * v2.w + w3 * v3.w;
    }
    for (; j < e; j++) {
        int2 sv = g_slot[j];
        float w = __int_as_float(sv.y);
        float4 v = h4_to_f4(g_xh[(size_t)sv.x * 32 + lane]);
        acc.x += w * v.x; acc.y += w * v.y;
        acc.z += w * v.z; acc.w += w * v.w;
    }

    // eagg @ W_edge: eagg row in lanes 0..3 (lane sl holds k = 4*sl + c)
    float4 ea = make_float4(0.f, 0.f, 0.f, 0.f);
    if (lane < (DE / 4)) ea = g_eagg[(size_t)node * (DE / 4) + lane];
    #pragma unroll
    for (int sl = 0; sl < 4; sl++) {
        float e0 = __shfl_sync(FULLM, ea.x, sl);
        float e1 = __shfl_sync(FULLM, ea.y, sl);
        float e2 = __shfl_sync(FULLM, ea.z, sl);
        float e3 = __shfl_sync(FULLM, ea.w, sl);
        float4 w0 = We4[(4 * sl + 0) * (D / 4) + lane];
        float4 w1 = We4[(4 * sl + 1) * (D / 4) + lane];
        float4 w2 = We4[(4 * sl + 2) * (D / 4) + lane];
        float4 w3 = We4[(4 * sl + 3) * (D / 4) + lane];
        acc.x += e0 * w0.x + e1 * w1.x + e2 * w2.x + e3 * w3.x;
        acc.y += e0 * w0.y + e1 * w1.y + e2 * w2.y + e3 * w3.y;
        acc.z += e0 * w0.z + e1 * w1.z + e2 * w2.z + e3 * w3.z;
        acc.w += e0 * w0.w + e1 * w1.w + e2 * w2.w + e3 * w3.w;
    }

    float4 xs = x4[(size_t)node * (D / 4) + lane];
    float4 bb = be4[lane];
    acc.x += xs.x + bb.x; acc.y += xs.y + bb.y;
    acc.z += xs.z + bb.z; acc.w += xs.w + bb.w;

    float4 ht;
    ht.x = __uint_as_float(f2tf(acc.x));
    ht.y = __uint_as_float(f2tf(acc.y));
    ht.z = __uint_as_float(f2tf(acc.z));
    ht.w = __uint_as_float(f2tf(acc.w));
    g_h[(size_t)node * (D / 4) + lane] = ht;
}

// ---------------------------------------------------------------------------
// K5: node MLP via tf32 MMA (m16n8k8), fp32 accumulate.
// 128 nodes/block, 512 threads.  Warp w: 16 nodes (w&7) x 64 cols (w>>3).
// Weights pre-converted col-major; all fragment loads conflict-free.
// ---------------------------------------------------------------------------
__global__ __launch_bounds__(512, 1) void k_mlp(
    const float* __restrict__ b1,
    const float* __restrict__ b2,
    float* __restrict__ out)
{
    extern __shared__ float smem[];
    float* sW1 = smem;                 // 128 * 132 floats, col-major [c][k]
    float* sW2 = sW1 + D * WS;
    float* sh  = sW2 + D * WS;         // 128 * 132 floats, row-major [n][k]

    const int tid  = threadIdx.x;
    const int base = blockIdx.x * MLP_N;

    // Stage: pure copies (weights already tf32 + transposed; h already tf32)
    {
        const uint4* w1v = (const uint4*)g_w1t;
        const uint4* w2v = (const uint4*)g_w2t;
        for (int i = tid; i < 4096; i += 512) {
            int c = i >> 5, k4 = i & 31;
            *(uint4*)(sW1 + c * WS + k4 * 4) = w1v[(c * WS) / 4 + k4];
            *(uint4*)(sW2 + c * WS + k4 * 4) = w2v[(c * WS) / 4 + k4];
        }
        for (int i = tid; i < MLP_N * 32; i += 512) {
            int n = i >> 5, c4 = i & 31;
            *(float4*)(sh + n * WS + c4 * 4) = g_h[(size_t)(base + n) * 32 + c4];
        }
    }
    __syncthreads();

    const int lane  = tid & 31;
    const int warp  = tid >> 5;
    const int gid   = lane >> 2;    // 0..7
    const int tig   = lane & 3;     // 0..3
    const int nbase = (warp & 7) * 16;   // 0..112
    const int cbase = (warp >> 3) * 64;  // 0 or 64

    const unsigned* ush = (const unsigned*)sh;
    const unsigned* uw1 = (const unsigned*)sW1;
    const unsigned* uw2 = (const unsigned*)sW2;

    float c[8][4];

    // ---- Layer 1 ----
    #pragma unroll
    for (int ct = 0; ct < 8; ct++) {
        int col0 = cbase + ct * 8 + 2 * tig;
        float2 bb = *(const float2*)(b1 + col0);
        c[ct][0] = bb.x; c[ct][1] = bb.y; c[ct][2] = bb.x; c[ct][3] = bb.y;
    }
    #pragma unroll 4
    for (int k0 = 0; k0 < 128; k0 += 8) {
        unsigned a0 = ush[(nbase + gid)     * WS + k0 + tig];
        unsigned a1 = ush[(nbase + gid + 8) * WS + k0 + tig];
        unsigned a2 = ush[(nbase + gid)     * WS + k0 + tig + 4];
        unsigned a3 = ush[(nbase + gid + 8) * WS + k0 + tig + 4];
        #pragma unroll
        for (int ct = 0; ct < 8; ct++) {
            int cc = cbase + ct * 8 + gid;
            unsigned bb0 = uw1[cc * WS + k0 + tig];
            unsigned bb1 = uw1[cc * WS + k0 + tig + 4];
            mma_tf32(c[ct][0], c[ct][1], c[ct][2], c[ct][3],
                     a0, a1, a2, a3, bb0, bb1);
        }
    }
    __syncthreads();   // all layer-1 A reads done before sh overwrite

    // ReLU + tf32 round + write h1 back to sh
    {
        unsigned* wsh = (unsigned*)sh;
        #pragma unroll
        for (int ct = 0; ct < 8; ct++) {
            int col0 = cbase + ct * 8 + 2 * tig;
            unsigned t0 = f2tf(fmaxf(c[ct][0], 0.f));
            unsigned t1 = f2tf(fmaxf(c[ct][1], 0.f));
            unsigned t2 = f2tf(fmaxf(c[ct][2], 0.f));
            unsigned t3 = f2tf(fmaxf(c[ct][3], 0.f));
            *(uint2*)(wsh + (nbase + gid)     * WS + col0) = make_uint2(t0, t1);
            *(uint2*)(wsh + (nbase + gid + 8) * WS + col0) = make_uint2(t2, t3);
        }
    }
    __syncthreads();

    // ---- Layer 2 ----
    #pragma unroll
    for (int ct = 0; ct < 8; ct++) {
        int col0 = cbase + ct * 8 + 2 * tig;
        float2 bb = *(const float2*)(b2 + col0);
        c[ct][0] = bb.x; c[ct][1] = bb.y; c[ct][2] = bb.x; c[ct][3] = bb.y;
    }
    #pragma unroll 4
    for (int k0 = 0; k0 < 128; k0 += 8) {
        unsigned a0 = ush[(nbase + gid)     * WS + k0 + tig];
        unsigned a1 = ush[(nbase + gid + 8) * WS + k0 + tig];
        unsigned a2 = ush[(nbase + gid)     * WS + k0 + tig + 4];
        unsigned a3 = ush[(nbase + gid + 8) * WS + k0 + tig + 4];
        #pragma unroll
        for (int ct = 0; ct < 8; ct++) {
            int cc = cbase + ct * 8 + gid;
            unsigned bb0 = uw2[cc * WS + k0 + tig];
            unsigned bb1 = uw2[cc * WS + k0 + tig + 4];
            mma_tf32(c[ct][0], c[ct][1], c[ct][2], c[ct][3],
                     a0, a1, a2, a3, bb0, bb1);
        }
    }

    // Final ReLU + global store (float2 per fragment row)
    {
        int node0 = base + nbase + gid;
        int node1 = node0 + 8;
        #pragma unroll
        for (int ct = 0; ct < 8; ct++) {
            int col0 = cbase + ct * 8 + 2 * tig;
            if (node0 < N_NODE) {
                float2 r0 = make_float2(fmaxf(c[ct][0], 0.f), fmaxf(c[ct][1], 0.f));
                *(float2*)(out + (size_t)node0 * D + col0) = r0;
            }
            if (node1 < N_NODE) {
                float2 r1 = make_float2(fmaxf(c[ct][2], 0.f), fmaxf(c[ct][3], 0.f));
                *(float2*)(out + (size_t)node1 * D + col0) = r1;
            }
        }
    }
}

// ---------------------------------------------------------------------------
// Launch
// ---------------------------------------------------------------------------
extern "C" void kernel_launch(void* const* d_in, const int* in_sizes, int n_in,
                              void* d_out, int out_size)
{
    const int2*  edge_list   = (const int2*)d_in[0];
    const float* edge_weight = (const float*)d_in[1];
    const float* edge_feat   = (const float*)d_in[2];
    // d_in[3] = num_node (constant)
    const float* x  = (const float*)d_in[4];
    const float* We = (const float*)d_in[5];
    const float* be = (const float*)d_in[6];
    const float* W1 = (const float*)d_in[7];
    const float* b1 = (const float*)d_in[8];
    const float* W2 = (const float*)d_in[9];
    const float* b2 = (const float*)d_in[10];
    float* out = (float*)d_out;

    const int smem_bytes = (D * WS * 2 + MLP_N * WS) * 4;   // 202752 B
    cudaFuncSetAttribute(k_mlp, cudaFuncAttributeMaxDynamicSharedMemorySize, smem_bytes);

    void* p_cnt  = nullptr;
    void* p_done = nullptr;
    cudaGetSymbolAddress(&p_cnt,  g_cnt);
    cudaGetSymbolAddress(&p_done, g_done);
    cudaMemsetAsync(p_cnt,  0, sizeof(int) * N_NODE);
    cudaMemsetAsync(p_done, 0, sizeof(int));

    k_hist<<<(N_EDGE + 255) / 256, 256>>>(edge_list);
    k_scan<<<NBLK, 1024>>>((const float4*)x, W1, W2);
    k_reorder<<<(N_EDGE + 255) / 256, 256>>>(edge_list, edge_weight, edge_feat);
    k_gather<<<N_NODE / 8, 256>>>(x, We, be);
    k_mlp<<<(N_NODE + MLP_N - 1) / MLP_N, 512, smem_bytes>>>(b1, b2, out);
}